// round 5
// baseline (speedup 1.0000x reference)
#include <cuda_runtime.h>
#include <cuda_bf16.h>
#include <cstdint>

#define NNODES 100000
#define NEDGES 300000
#define GDIM   2048
#define HIDDIM 256
#define EDIM   64
#define NLAYER 3
#define NBLK   ((NNODES + 255) / 256)   // 391

// ---------------- static device scratch ----------------
__device__ float g_bufA[(size_t)NNODES * HIDDIM];
__device__ float g_bufB[(size_t)NNODES * HIDDIM];
__device__ float g_xl[(size_t)NNODES * HIDDIM];
__device__ float g_xr[(size_t)NNODES * HIDDIM];
__device__ float g_easorted[(size_t)NEDGES * EDIM];  // edge_attr permuted to dst-sorted order
__device__ float g_p[(size_t)NEDGES * 4];            // exp(logit) per edge/head, dst-sorted
__device__ float g_eloop[HIDDIM];
__device__ float g_esum[EDIM];
__device__ float g_gsum[(size_t)GDIM * HIDDIM];
__device__ float g_gcnt[GDIM];
// CSR (dst-sorted edges)
__device__ int g_cnt[NNODES];
__device__ int g_bsum[512];
__device__ int g_rowptr[NNODES + 1];
__device__ int g_woff[NNODES];
__device__ int g_ssrc[NEDGES];
__device__ int g_sdst[NEDGES];
__device__ int g_seid[NEDGES];

// ---------------- helpers ----------------
__device__ __forceinline__ void red4(float* p, float a, float b, float c, float d) {
    asm volatile("red.global.add.v4.f32 [%0], {%1,%2,%3,%4};"
                 :: "l"(p), "f"(a), "f"(b), "f"(c), "f"(d) : "memory");
}
__device__ __forceinline__ void mma_tf32(float* c, const uint32_t* a, const uint32_t* b) {
    asm volatile("mma.sync.aligned.m16n8k8.row.col.f32.tf32.tf32.f32 "
                 "{%0,%1,%2,%3}, {%4,%5,%6,%7}, {%8,%9}, {%0,%1,%2,%3};"
                 : "+f"(c[0]), "+f"(c[1]), "+f"(c[2]), "+f"(c[3])
                 : "r"(a[0]), "r"(a[1]), "r"(a[2]), "r"(a[3]), "r"(b[0]), "r"(b[1]));
}

// ---------------- tf32 GEMM with register-prefetch double buffering ----------------
// C[M,256] = A[M,K] @ W[K,256] (+bias). CTA tile 128x128, BK=32, 8 warps 4x2.
template<int K, bool HASBIAS>
__global__ __launch_bounds__(256)
void gemm_mma(const float* __restrict__ A, const float* __restrict__ W,
              const float* __restrict__ bias, float* __restrict__ C, int M) {
    __shared__ __align__(16) float As[128][36];
    __shared__ __align__(16) float Bs[32][136];
    const int tid = threadIdx.x, warp = tid >> 5, lane = tid & 31;
    const int warp_m = warp & 3, warp_n = warp >> 2;
    const int row0 = blockIdx.x * 128, col0 = blockIdx.y * 128;
    const int lq = lane >> 2, lr = lane & 3;

    float acc[2][8][4];
#pragma unroll
    for (int mt = 0; mt < 2; mt++)
#pragma unroll
        for (int nt = 0; nt < 8; nt++)
#pragma unroll
            for (int i = 0; i < 4; i++) acc[mt][nt][i] = 0.0f;

    float4 pa[4], pb[4];
#pragma unroll
    for (int i = 0; i < 4; i++) {
        int idx = tid + i * 256;
        int r = idx >> 3, q = idx & 7;
        int ar = row0 + r; if (ar >= M) ar = M - 1;
        pa[i] = *(const float4*)(A + (size_t)ar * K + q * 4);
        int rb = idx >> 5, qb = idx & 31;
        pb[i] = *(const float4*)(W + (size_t)rb * 256 + col0 + qb * 4);
    }

    for (int k0 = 0; k0 < K; k0 += 32) {
#pragma unroll
        for (int i = 0; i < 4; i++) {
            int idx = tid + i * 256;
            int r = idx >> 3, q = idx & 7;
            *(float4*)&As[r][q * 4] = pa[i];
            int rb = idx >> 5, qb = idx & 31;
            *(float4*)&Bs[rb][qb * 4] = pb[i];
        }
        __syncthreads();
        if (k0 + 32 < K) {
#pragma unroll
            for (int i = 0; i < 4; i++) {
                int idx = tid + i * 256;
                int r = idx >> 3, q = idx & 7;
                int ar = row0 + r; if (ar >= M) ar = M - 1;
                pa[i] = *(const float4*)(A + (size_t)ar * K + k0 + 32 + q * 4);
                int rb = idx >> 5, qb = idx & 31;
                pb[i] = *(const float4*)(W + (size_t)(k0 + 32 + rb) * 256 + col0 + qb * 4);
            }
        }
#pragma unroll
        for (int ks = 0; ks < 4; ks++) {
            const int kb = ks * 8;
            uint32_t bf[8][2];
            const int brow = kb + lr, bcol = warp_n * 64 + lq;
#pragma unroll
            for (int nt = 0; nt < 8; nt++) {
                bf[nt][0] = __float_as_uint(Bs[brow][bcol + nt * 8]);
                bf[nt][1] = __float_as_uint(Bs[brow + 4][bcol + nt * 8]);
            }
#pragma unroll
            for (int mt = 0; mt < 2; mt++) {
                uint32_t af[4];
                const int arow = warp_m * 32 + mt * 16 + lq;
                af[0] = __float_as_uint(As[arow][kb + lr]);
                af[1] = __float_as_uint(As[arow + 8][kb + lr]);
                af[2] = __float_as_uint(As[arow][kb + 4 + lr]);
                af[3] = __float_as_uint(As[arow + 8][kb + 4 + lr]);
#pragma unroll
                for (int nt = 0; nt < 8; nt++) mma_tf32(acc[mt][nt], af, bf[nt]);
            }
        }
        __syncthreads();
    }

    const int r_base = row0 + warp_m * 32 + lq;
    const int c_base = col0 + warp_n * 64 + lr * 2;
#pragma unroll
    for (int nt = 0; nt < 8; nt++) {
        int c = c_base + nt * 8;
        float2 bv = make_float2(0.f, 0.f);
        if (HASBIAS) bv = *(const float2*)(bias + c);
#pragma unroll
        for (int mt = 0; mt < 2; mt++) {
            int r = r_base + mt * 16;
            if (r < M) {
                float2 o0 = make_float2(acc[mt][nt][0] + bv.x, acc[mt][nt][1] + bv.y);
                *(float2*)(C + (size_t)r * 256 + c) = o0;
            }
            if (r + 8 < M) {
                float2 o1 = make_float2(acc[mt][nt][2] + bv.x, acc[mt][nt][3] + bv.y);
                *(float2*)(C + (size_t)(r + 8) * 256 + c) = o1;
            }
        }
    }
}

// ---------------- edge GEMM fused with logit epilogue ----------------
// Rows = dst-sorted edges (A = g_easorted, K=64). Instead of writing eproj,
// gathers xl[src], xr[dst], applies lrelu + att-dot, writes p = exp(logit).
// Each warp's 64-col slice == one head (head = blockIdx.y*2 + warp_n).
__global__ __launch_bounds__(256)
void edge_logit_mma(const float* __restrict__ W, const float* __restrict__ att) {
    __shared__ __align__(16) float As[128][36];
    __shared__ __align__(16) float Bs[32][136];
    const float* A = g_easorted;
    const int K = 64, M = NEDGES;
    const int tid = threadIdx.x, warp = tid >> 5, lane = tid & 31;
    const int warp_m = warp & 3, warp_n = warp >> 2;
    const int row0 = blockIdx.x * 128, col0 = blockIdx.y * 128;
    const int lq = lane >> 2, lr = lane & 3;

    float acc[2][8][4];
#pragma unroll
    for (int mt = 0; mt < 2; mt++)
#pragma unroll
        for (int nt = 0; nt < 8; nt++)
#pragma unroll
            for (int i = 0; i < 4; i++) acc[mt][nt][i] = 0.0f;

    float4 pa[4], pb[4];
#pragma unroll
    for (int i = 0; i < 4; i++) {
        int idx = tid + i * 256;
        int r = idx >> 3, q = idx & 7;
        int ar = row0 + r; if (ar >= M) ar = M - 1;
        pa[i] = *(const float4*)(A + (size_t)ar * K + q * 4);
        int rb = idx >> 5, qb = idx & 31;
        pb[i] = *(const float4*)(W + (size_t)rb * 256 + col0 + qb * 4);
    }
    for (int k0 = 0; k0 < K; k0 += 32) {
#pragma unroll
        for (int i = 0; i < 4; i++) {
            int idx = tid + i * 256;
            int r = idx >> 3, q = idx & 7;
            *(float4*)&As[r][q * 4] = pa[i];
            int rb = idx >> 5, qb = idx & 31;
            *(float4*)&Bs[rb][qb * 4] = pb[i];
        }
        __syncthreads();
        if (k0 + 32 < K) {
#pragma unroll
            for (int i = 0; i < 4; i++) {
                int idx = tid + i * 256;
                int r = idx >> 3, q = idx & 7;
                int ar = row0 + r; if (ar >= M) ar = M - 1;
                pa[i] = *(const float4*)(A + (size_t)ar * K + k0 + 32 + q * 4);
                int rb = idx >> 5, qb = idx & 31;
                pb[i] = *(const float4*)(W + (size_t)(k0 + 32 + rb) * 256 + col0 + qb * 4);
            }
        }
#pragma unroll
        for (int ks = 0; ks < 4; ks++) {
            const int kb = ks * 8;
            uint32_t bf[8][2];
            const int brow = kb + lr, bcol = warp_n * 64 + lq;
#pragma unroll
            for (int nt = 0; nt < 8; nt++) {
                bf[nt][0] = __float_as_uint(Bs[brow][bcol + nt * 8]);
                bf[nt][1] = __float_as_uint(Bs[brow + 4][bcol + nt * 8]);
            }
#pragma unroll
            for (int mt = 0; mt < 2; mt++) {
                uint32_t af[4];
                const int arow = warp_m * 32 + mt * 16 + lq;
                af[0] = __float_as_uint(As[arow][kb + lr]);
                af[1] = __float_as_uint(As[arow + 8][kb + lr]);
                af[2] = __float_as_uint(As[arow][kb + 4 + lr]);
                af[3] = __float_as_uint(As[arow + 8][kb + 4 + lr]);
#pragma unroll
                for (int nt = 0; nt < 8; nt++) mma_tf32(acc[mt][nt], af, bf[nt]);
            }
        }
        __syncthreads();
    }

    // ---- fused logit epilogue ----
    const int head = blockIdx.y * 2 + warp_n;
    // att values for this thread's 16 columns
    float av[8][2];
#pragma unroll
    for (int nt = 0; nt < 8; nt++) {
        float2 a2 = *(const float2*)(att + col0 + warp_n * 64 + lr * 2 + nt * 8);
        av[nt][0] = a2.x; av[nt][1] = a2.y;
    }
    // rows handled by this thread: warp_m*32 + lq + {0,8,16,24}
#pragma unroll
    for (int rr = 0; rr < 4; rr++) {
        int mt = rr >> 1, half = rr & 1;           // half: 0 -> acc[.][.][0,1], 1 -> [2,3]
        int rloc = warp_m * 32 + mt * 16 + half * 8 + lq;
        int row = row0 + rloc;
        int rc = (row < M) ? row : M - 1;
        int s = g_ssrc[rc], d = g_sdst[rc];
        const float* xls = g_xl + (size_t)s * 256;
        const float* xrd = g_xr + (size_t)d * 256;
        float t = 0.0f;
#pragma unroll
        for (int nt = 0; nt < 8; nt++) {
            int c = col0 + warp_n * 64 + lr * 2 + nt * 8;
            float2 xl2 = *(const float2*)(xls + c);
            float2 xr2 = *(const float2*)(xrd + c);
            float m0 = acc[mt][nt][half * 2 + 0] + xl2.x + xr2.x;
            float m1 = acc[mt][nt][half * 2 + 1] + xl2.y + xr2.y;
            m0 = fmaxf(m0, 0.2f * m0);
            m1 = fmaxf(m1, 0.2f * m1);
            t = fmaf(m0, av[nt][0], t);
            t = fmaf(m1, av[nt][1], t);
        }
        // quad reduce (lanes lr=0..3 share the same row)
        t += __shfl_xor_sync(0xffffffffu, t, 1, 4);
        t += __shfl_xor_sync(0xffffffffu, t, 2, 4);
        if (lr == 0 && row < M) g_p[(size_t)row * 4 + head] = __expf(t);
    }
}

// ---------------- CSR build (once per launch) ----------------
__global__ void hist_kernel(const int* __restrict__ dst) {
    int e = blockIdx.x * blockDim.x + threadIdx.x;
    if (e < NEDGES) atomicAdd(&g_cnt[dst[e]], 1);
}
__global__ void blocksum_kernel() {
    int i = blockIdx.x * 256 + threadIdx.x;
    int v = (i < NNODES) ? g_cnt[i] : 0;
    __shared__ int ws[8];
#pragma unroll
    for (int o = 16; o; o >>= 1) v += __shfl_down_sync(0xffffffffu, v, o);
    if ((threadIdx.x & 31) == 0) ws[threadIdx.x >> 5] = v;
    __syncthreads();
    if (threadIdx.x == 0) {
        int s = 0;
#pragma unroll
        for (int j = 0; j < 8; j++) s += ws[j];
        g_bsum[blockIdx.x] = s;
    }
}
__global__ void scanb_kernel() {
    __shared__ int sm[512];
    int i = threadIdx.x;
    int v = (i < NBLK) ? g_bsum[i] : 0;
    sm[i] = v;
    __syncthreads();
    for (int s = 1; s < 512; s <<= 1) {
        int t = (i >= s) ? sm[i - s] : 0;
        __syncthreads();
        sm[i] += t;
        __syncthreads();
    }
    if (i < NBLK) g_bsum[i] = sm[i] - v;
}
__global__ void rowptr_kernel() {
    int tid = threadIdx.x;
    int i = blockIdx.x * 256 + tid;
    int v = (i < NNODES) ? g_cnt[i] : 0;
    __shared__ int sm[256];
    sm[tid] = v;
    __syncthreads();
    for (int s = 1; s < 256; s <<= 1) {
        int t = (tid >= s) ? sm[tid - s] : 0;
        __syncthreads();
        sm[tid] += t;
        __syncthreads();
    }
    int ex = sm[tid] - v + g_bsum[blockIdx.x];
    if (i < NNODES) { g_rowptr[i] = ex; g_woff[i] = ex; }
    if (i == NNODES - 1) g_rowptr[NNODES] = NEDGES;
}
__global__ void fill_kernel(const int* __restrict__ src, const int* __restrict__ dst) {
    int e = blockIdx.x * blockDim.x + threadIdx.x;
    if (e >= NEDGES) return;
    int d = dst[e];
    int pos = atomicAdd(&g_woff[d], 1);
    g_ssrc[pos] = src[e];
    g_sdst[pos] = d;
    g_seid[pos] = e;
}
// permute edge_attr into dst-sorted order
__global__ void permute_ea_kernel(const float* __restrict__ ea) {
    int gt = blockIdx.x * blockDim.x + threadIdx.x;   // over NEDGES*16 float4s
    if (gt >= NEDGES * 16) return;
    int i = gt >> 4, q = gt & 15;
    int e = g_seid[i];
    ((float4*)g_easorted)[(size_t)i * 16 + q] = ((const float4*)ea)[(size_t)e * 16 + q];
}

// ---------------- edge_attr column sums (once) ----------------
__global__ void esum_kernel(const float* __restrict__ ea) {
    int col = threadIdx.x & 63;
    int rowsPerBlk = blockDim.x >> 6;
    int r0 = blockIdx.x * rowsPerBlk + (threadIdx.x >> 6);
    int rstride = gridDim.x * rowsPerBlk;
    float s = 0.0f;
    for (int r = r0; r < NEDGES; r += rstride) s += ea[(size_t)r * EDIM + col];
    atomicAdd(&g_esum[col], s);
}
__global__ void eloop_kernel(const float* __restrict__ We) {
    int j = threadIdx.x;
    const float inv = 1.0f / (float)NEDGES;
    float acc = 0.0f;
#pragma unroll
    for (int k = 0; k < EDIM; k++) acc = fmaf(g_esum[k] * inv, We[k * 256 + j], acc);
    g_eloop[j] = acc;
}

// ---------------- aggregate: warp per dst node ----------------
// out[d] = relu( (p_self*xl[d] + sum_e p_e*xl[src_e]) / (p_self + sum_e p_e) + bias )
__global__ __launch_bounds__(256)
void aggregate_kernel(const float* __restrict__ att, const float* __restrict__ bias,
                      float* __restrict__ xn) {
    int gt = blockIdx.x * blockDim.x + threadIdx.x;
    int d = gt >> 5, lane = gt & 31;
    if (d >= NNODES) return;
    const int off = lane * 8;
    const int h = lane >> 3;

    float acc[8];
    float denom;
    // ---- self loop ----
    {
        float4 xr0 = *(const float4*)(g_xr + (size_t)d * 256 + off);
        float4 xr1 = *(const float4*)(g_xr + (size_t)d * 256 + off + 4);
        float4 at0 = *(const float4*)(att + off);
        float4 at1 = *(const float4*)(att + off + 4);
        float4 a0 = *(const float4*)(g_xl + (size_t)d * 256 + off);
        float4 a1 = *(const float4*)(g_xl + (size_t)d * 256 + off + 4);
        float4 e0 = *(const float4*)(g_eloop + off);
        float4 e1 = *(const float4*)(g_eloop + off + 4);
        float t = 0.0f, m;
        m = a0.x + xr0.x + e0.x; m = fmaxf(m, 0.2f * m); t = fmaf(m, at0.x, t);
        m = a0.y + xr0.y + e0.y; m = fmaxf(m, 0.2f * m); t = fmaf(m, at0.y, t);
        m = a0.z + xr0.z + e0.z; m = fmaxf(m, 0.2f * m); t = fmaf(m, at0.z, t);
        m = a0.w + xr0.w + e0.w; m = fmaxf(m, 0.2f * m); t = fmaf(m, at0.w, t);
        m = a1.x + xr1.x + e1.x; m = fmaxf(m, 0.2f * m); t = fmaf(m, at1.x, t);
        m = a1.y + xr1.y + e1.y; m = fmaxf(m, 0.2f * m); t = fmaf(m, at1.y, t);
        m = a1.z + xr1.z + e1.z; m = fmaxf(m, 0.2f * m); t = fmaf(m, at1.z, t);
        m = a1.w + xr1.w + e1.w; m = fmaxf(m, 0.2f * m); t = fmaf(m, at1.w, t);
        t += __shfl_down_sync(0xffffffffu, t, 4, 8);
        t += __shfl_down_sync(0xffffffffu, t, 2, 8);
        t += __shfl_down_sync(0xffffffffu, t, 1, 8);
        float p = __expf(__shfl_sync(0xffffffffu, t, 0, 8));
        denom = p;
        acc[0] = p * a0.x; acc[1] = p * a0.y; acc[2] = p * a0.z; acc[3] = p * a0.w;
        acc[4] = p * a1.x; acc[5] = p * a1.y; acc[6] = p * a1.z; acc[7] = p * a1.w;
    }
    // ---- real edges ----
    const int beg = g_rowptr[d], end = g_rowptr[d + 1];
    for (int i = beg; i < end; i++) {
        int s = g_ssrc[i];
        float p = g_p[(size_t)i * 4 + h];
        float4 a0 = *(const float4*)(g_xl + (size_t)s * 256 + off);
        float4 a1 = *(const float4*)(g_xl + (size_t)s * 256 + off + 4);
        denom += p;
        acc[0] = fmaf(p, a0.x, acc[0]); acc[1] = fmaf(p, a0.y, acc[1]);
        acc[2] = fmaf(p, a0.z, acc[2]); acc[3] = fmaf(p, a0.w, acc[3]);
        acc[4] = fmaf(p, a1.x, acc[4]); acc[5] = fmaf(p, a1.y, acc[5]);
        acc[6] = fmaf(p, a1.z, acc[6]); acc[7] = fmaf(p, a1.w, acc[7]);
    }
    float inv = 1.0f / (denom + 1e-16f);
    float4 b0 = *(const float4*)(bias + off);
    float4 b1 = *(const float4*)(bias + off + 4);
    float4 o0, o1;
    o0.x = fmaxf(fmaf(acc[0], inv, b0.x), 0.f); o0.y = fmaxf(fmaf(acc[1], inv, b0.y), 0.f);
    o0.z = fmaxf(fmaf(acc[2], inv, b0.z), 0.f); o0.w = fmaxf(fmaf(acc[3], inv, b0.w), 0.f);
    o1.x = fmaxf(fmaf(acc[4], inv, b1.x), 0.f); o1.y = fmaxf(fmaf(acc[5], inv, b1.y), 0.f);
    o1.z = fmaxf(fmaf(acc[6], inv, b1.z), 0.f); o1.w = fmaxf(fmaf(acc[7], inv, b1.w), 0.f);
    *(float4*)(xn + (size_t)d * 256 + off) = o0;
    *(float4*)(xn + (size_t)d * 256 + off + 4) = o1;
}

// ---------------- global mean pool ----------------
__global__ void pool_kernel(const int* __restrict__ batch, const float* __restrict__ xf) {
    int gt = blockIdx.x * blockDim.x + threadIdx.x;
    int node = gt >> 5, lane = gt & 31;
    if (node >= NNODES) return;
    int g = batch[node];
    const float4* xs = (const float4*)(xf + (size_t)node * 256) + lane * 2;
    float4 v0 = xs[0], v1 = xs[1];
    float* bp = g_gsum + (size_t)g * 256 + lane * 8;
    red4(bp,     v0.x, v0.y, v0.z, v0.w);
    red4(bp + 4, v1.x, v1.y, v1.z, v1.w);
    if (lane == 0) atomicAdd(&g_gcnt[g], 1.0f);
}

// ---------------- final MLP ----------------
__global__ __launch_bounds__(128)
void mlp_kernel(const float* __restrict__ Wp1, const float* __restrict__ bp1,
                const float* __restrict__ Wp2, const float* __restrict__ bp2,
                float* __restrict__ out) {
    int g = blockIdx.x;
    __shared__ float pooled[256];
    __shared__ float partial[4];
    float cnt = fmaxf(g_gcnt[g], 1.0f);
    for (int i = threadIdx.x; i < 256; i += 128)
        pooled[i] = g_gsum[(size_t)g * 256 + i] / cnt;
    __syncthreads();
    int j = threadIdx.x;
    float acc = bp1[j];
#pragma unroll 8
    for (int k = 0; k < 256; k++) acc = fmaf(pooled[k], Wp1[k * 128 + j], acc);
    float h = fmaxf(acc, 0.0f) * Wp2[j];
#pragma unroll
    for (int o = 16; o; o >>= 1) h += __shfl_down_sync(0xffffffffu, h, o);
    if ((threadIdx.x & 31) == 0) partial[threadIdx.x >> 5] = h;
    __syncthreads();
    if (threadIdx.x == 0)
        out[g] = partial[0] + partial[1] + partial[2] + partial[3] + bp2[0];
}

// ---------------- launcher ----------------
extern "C" void kernel_launch(void* const* d_in, const int* in_sizes, int n_in,
                              void* d_out, int out_size) {
    const float* x     = (const float*)d_in[0];
    const int*   ei    = (const int*)  d_in[1];
    const float* ea    = (const float*)d_in[2];
    const int*   batch = (const int*)  d_in[3];
    const float* Wl    = (const float*)d_in[4];
    const float* bl    = (const float*)d_in[5];
    const float* Wr    = (const float*)d_in[6];
    const float* br    = (const float*)d_in[7];
    const float* We    = (const float*)d_in[8];
    const float* att   = (const float*)d_in[9];
    const float* bias  = (const float*)d_in[10];
    const float* Wp1   = (const float*)d_in[11];
    const float* bp1   = (const float*)d_in[12];
    const float* Wp2   = (const float*)d_in[13];
    const float* bp2   = (const float*)d_in[14];
    float* out = (float*)d_out;
    const int* src = ei;
    const int* dst = ei + NEDGES;

    float *bufA, *bufB, *xl, *xr, *esum, *gsum, *gcnt;
    int* cnt;
    cudaGetSymbolAddress((void**)&bufA,  g_bufA);
    cudaGetSymbolAddress((void**)&bufB,  g_bufB);
    cudaGetSymbolAddress((void**)&xl,    g_xl);
    cudaGetSymbolAddress((void**)&xr,    g_xr);
    cudaGetSymbolAddress((void**)&esum,  g_esum);
    cudaGetSymbolAddress((void**)&gsum,  g_gsum);
    cudaGetSymbolAddress((void**)&gcnt,  g_gcnt);
    cudaGetSymbolAddress((void**)&cnt,   g_cnt);

    // ---- CSR build + ea permutation (topology constant) ----
    cudaMemsetAsync(cnt, 0, NNODES * sizeof(int));
    hist_kernel<<<(NEDGES + 255) / 256, 256>>>(dst);
    blocksum_kernel<<<NBLK, 256>>>();
    scanb_kernel<<<1, 512>>>();
    rowptr_kernel<<<NBLK, 256>>>();
    fill_kernel<<<(NEDGES + 255) / 256, 256>>>(src, dst);
    permute_ea_kernel<<<(NEDGES * 16 + 255) / 256, 256>>>(ea);

    cudaMemsetAsync(esum, 0, EDIM * sizeof(float));
    esum_kernel<<<512, 256>>>(ea);

    const float* xcur = x;
    for (int l = 0; l < NLAYER; l++) {
        float* xn = (l & 1) ? bufB : bufA;
        dim3 gN((NNODES + 127) / 128, 2);
        gemm_mma<256, true><<<gN, 256>>>(xcur, Wl + (size_t)l * 256 * 256, bl + l * 256, xl, NNODES);
        gemm_mma<256, true><<<gN, 256>>>(xcur, Wr + (size_t)l * 256 * 256, br + l * 256, xr, NNODES);
        eloop_kernel<<<1, 256>>>(We + (size_t)l * 64 * 256);

        dim3 gE((NEDGES + 127) / 128, 2);
        edge_logit_mma<<<gE, 256>>>(We + (size_t)l * 64 * 256, att + l * 256);
        aggregate_kernel<<<(NNODES * 32 + 255) / 256, 256>>>(att + l * 256, bias + l * 256, xn);
        xcur = xn;
    }

    cudaMemsetAsync(gsum, 0, (size_t)GDIM * 256 * sizeof(float));
    cudaMemsetAsync(gcnt, 0, GDIM * sizeof(float));
    pool_kernel<<<(NNODES * 32 + 255) / 256, 256>>>(batch, xcur);
    mlp_kernel<<<GDIM, 128>>>(Wp1, bp1, Wp2, bp2, out);
}

// round 6
// speedup vs baseline: 1.0883x; 1.0883x over previous
#include <cuda_runtime.h>
#include <cuda_bf16.h>
#include <cstdint>

#define NNODES 100000
#define NEDGES 300000
#define GDIM   2048
#define HIDDIM 256
#define EDIM   64
#define NLAYER 3
#define NBLK   ((NNODES + 255) / 256)   // 391

// ---------------- static device scratch ----------------
__device__ float g_bufA[(size_t)NNODES * HIDDIM];
__device__ float g_bufB[(size_t)NNODES * HIDDIM];
__device__ float g_xl[(size_t)NNODES * HIDDIM];
__device__ float g_xr[(size_t)NNODES * HIDDIM];
__device__ float g_eproj[(size_t)NEDGES * HIDDIM];
__device__ float g_eloop[HIDDIM];
__device__ float g_esum[EDIM];
__device__ float g_gsum[(size_t)GDIM * HIDDIM];
__device__ float g_gcnt[GDIM];
// CSR (dst-sorted edges)
__device__ int g_cnt[NNODES];
__device__ int g_bsum[512];
__device__ int g_rowptr[NNODES + 1];
__device__ int g_woff[NNODES];
__device__ int g_ssrc[NEDGES];
__device__ int g_seid[NEDGES];

// ---------------- helpers ----------------
__device__ __forceinline__ void red4(float* p, float a, float b, float c, float d) {
    asm volatile("red.global.add.v4.f32 [%0], {%1,%2,%3,%4};"
                 :: "l"(p), "f"(a), "f"(b), "f"(c), "f"(d) : "memory");
}
__device__ __forceinline__ void mma_tf32(float* c, const uint32_t* a, const uint32_t* b) {
    asm volatile("mma.sync.aligned.m16n8k8.row.col.f32.tf32.tf32.f32 "
                 "{%0,%1,%2,%3}, {%4,%5,%6,%7}, {%8,%9}, {%0,%1,%2,%3};"
                 : "+f"(c[0]), "+f"(c[1]), "+f"(c[2]), "+f"(c[3])
                 : "r"(a[0]), "r"(a[1]), "r"(a[2]), "r"(a[3]), "r"(b[0]), "r"(b[1]));
}

// ---------------- tf32 GEMM with register-prefetch double buffering ----------------
// C[M,256] = A[M,K] @ W[K,256] (+bias). CTA tile 128x128, BK=32, 8 warps 4x2.
template<int K, bool HASBIAS>
__global__ __launch_bounds__(256)
void gemm_mma(const float* __restrict__ A, const float* __restrict__ W,
              const float* __restrict__ bias, float* __restrict__ C, int M) {
    __shared__ __align__(16) float As[128][36];
    __shared__ __align__(16) float Bs[32][136];
    const int tid = threadIdx.x, warp = tid >> 5, lane = tid & 31;
    const int warp_m = warp & 3, warp_n = warp >> 2;
    const int row0 = blockIdx.x * 128, col0 = blockIdx.y * 128;
    const int lq = lane >> 2, lr = lane & 3;

    float acc[2][8][4];
#pragma unroll
    for (int mt = 0; mt < 2; mt++)
#pragma unroll
        for (int nt = 0; nt < 8; nt++)
#pragma unroll
            for (int i = 0; i < 4; i++) acc[mt][nt][i] = 0.0f;

    float4 pa[4], pb[4];
#pragma unroll
    for (int i = 0; i < 4; i++) {
        int idx = tid + i * 256;
        int r = idx >> 3, q = idx & 7;
        int ar = row0 + r; if (ar >= M) ar = M - 1;
        pa[i] = *(const float4*)(A + (size_t)ar * K + q * 4);
        int rb = idx >> 5, qb = idx & 31;
        pb[i] = *(const float4*)(W + (size_t)rb * 256 + col0 + qb * 4);
    }

    for (int k0 = 0; k0 < K; k0 += 32) {
#pragma unroll
        for (int i = 0; i < 4; i++) {
            int idx = tid + i * 256;
            int r = idx >> 3, q = idx & 7;
            *(float4*)&As[r][q * 4] = pa[i];
            int rb = idx >> 5, qb = idx & 31;
            *(float4*)&Bs[rb][qb * 4] = pb[i];
        }
        __syncthreads();
        if (k0 + 32 < K) {
#pragma unroll
            for (int i = 0; i < 4; i++) {
                int idx = tid + i * 256;
                int r = idx >> 3, q = idx & 7;
                int ar = row0 + r; if (ar >= M) ar = M - 1;
                pa[i] = *(const float4*)(A + (size_t)ar * K + k0 + 32 + q * 4);
                int rb = idx >> 5, qb = idx & 31;
                pb[i] = *(const float4*)(W + (size_t)(k0 + 32 + rb) * 256 + col0 + qb * 4);
            }
        }
#pragma unroll
        for (int ks = 0; ks < 4; ks++) {
            const int kb = ks * 8;
            uint32_t bf[8][2];
            const int brow = kb + lr, bcol = warp_n * 64 + lq;
#pragma unroll
            for (int nt = 0; nt < 8; nt++) {
                bf[nt][0] = __float_as_uint(Bs[brow][bcol + nt * 8]);
                bf[nt][1] = __float_as_uint(Bs[brow + 4][bcol + nt * 8]);
            }
#pragma unroll
            for (int mt = 0; mt < 2; mt++) {
                uint32_t af[4];
                const int arow = warp_m * 32 + mt * 16 + lq;
                af[0] = __float_as_uint(As[arow][kb + lr]);
                af[1] = __float_as_uint(As[arow + 8][kb + lr]);
                af[2] = __float_as_uint(As[arow][kb + 4 + lr]);
                af[3] = __float_as_uint(As[arow + 8][kb + 4 + lr]);
#pragma unroll
                for (int nt = 0; nt < 8; nt++) mma_tf32(acc[mt][nt], af, bf[nt]);
            }
        }
        __syncthreads();
    }

    const int r_base = row0 + warp_m * 32 + lq;
    const int c_base = col0 + warp_n * 64 + lr * 2;
#pragma unroll
    for (int nt = 0; nt < 8; nt++) {
        int c = c_base + nt * 8;
        float2 bv = make_float2(0.f, 0.f);
        if (HASBIAS) bv = *(const float2*)(bias + c);
#pragma unroll
        for (int mt = 0; mt < 2; mt++) {
            int r = r_base + mt * 16;
            if (r < M) {
                float2 o0 = make_float2(acc[mt][nt][0] + bv.x, acc[mt][nt][1] + bv.y);
                *(float2*)(C + (size_t)r * 256 + c) = o0;
            }
            if (r + 8 < M) {
                float2 o1 = make_float2(acc[mt][nt][2] + bv.x, acc[mt][nt][3] + bv.y);
                *(float2*)(C + (size_t)(r + 8) * 256 + c) = o1;
            }
        }
    }
}

// ---------------- CSR build (once per launch) ----------------
__global__ void hist_kernel(const int* __restrict__ dst) {
    int e = blockIdx.x * blockDim.x + threadIdx.x;
    if (e < NEDGES) atomicAdd(&g_cnt[dst[e]], 1);
}
__global__ void blocksum_kernel() {
    int i = blockIdx.x * 256 + threadIdx.x;
    int v = (i < NNODES) ? g_cnt[i] : 0;
    __shared__ int ws[8];
#pragma unroll
    for (int o = 16; o; o >>= 1) v += __shfl_down_sync(0xffffffffu, v, o);
    if ((threadIdx.x & 31) == 0) ws[threadIdx.x >> 5] = v;
    __syncthreads();
    if (threadIdx.x == 0) {
        int s = 0;
#pragma unroll
        for (int j = 0; j < 8; j++) s += ws[j];
        g_bsum[blockIdx.x] = s;
    }
}
__global__ void scanb_kernel() {
    __shared__ int sm[512];
    int i = threadIdx.x;
    int v = (i < NBLK) ? g_bsum[i] : 0;
    sm[i] = v;
    __syncthreads();
    for (int s = 1; s < 512; s <<= 1) {
        int t = (i >= s) ? sm[i - s] : 0;
        __syncthreads();
        sm[i] += t;
        __syncthreads();
    }
    if (i < NBLK) g_bsum[i] = sm[i] - v;
}
__global__ void rowptr_kernel() {
    int tid = threadIdx.x;
    int i = blockIdx.x * 256 + tid;
    int v = (i < NNODES) ? g_cnt[i] : 0;
    __shared__ int sm[256];
    sm[tid] = v;
    __syncthreads();
    for (int s = 1; s < 256; s <<= 1) {
        int t = (tid >= s) ? sm[tid - s] : 0;
        __syncthreads();
        sm[tid] += t;
        __syncthreads();
    }
    int ex = sm[tid] - v + g_bsum[blockIdx.x];
    if (i < NNODES) { g_rowptr[i] = ex; g_woff[i] = ex; }
    if (i == NNODES - 1) g_rowptr[NNODES] = NEDGES;
}
__global__ void fill_kernel(const int* __restrict__ src, const int* __restrict__ dst) {
    int e = blockIdx.x * blockDim.x + threadIdx.x;
    if (e >= NEDGES) return;
    int d = dst[e];
    int pos = atomicAdd(&g_woff[d], 1);
    g_ssrc[pos] = src[e];
    g_seid[pos] = e;
}

// ---------------- edge_attr column sums (once) ----------------
__global__ void esum_kernel(const float* __restrict__ ea) {
    int col = threadIdx.x & 63;
    int rowsPerBlk = blockDim.x >> 6;
    int r0 = blockIdx.x * rowsPerBlk + (threadIdx.x >> 6);
    int rstride = gridDim.x * rowsPerBlk;
    float s = 0.0f;
    for (int r = r0; r < NEDGES; r += rstride) s += ea[(size_t)r * EDIM + col];
    atomicAdd(&g_esum[col], s);
}
__global__ void eloop_kernel(const float* __restrict__ We) {
    int j = threadIdx.x;
    const float inv = 1.0f / (float)NEDGES;
    float acc = 0.0f;
#pragma unroll
    for (int k = 0; k < EDIM; k++) acc = fmaf(g_esum[k] * inv, We[k * 256 + j], acc);
    g_eloop[j] = acc;
}

// ---------------- fused GAT edge phase: warp per dst node ----------------
__global__ __launch_bounds__(256)
void fused_gat_kernel(const float* __restrict__ att, const float* __restrict__ bias,
                      float* __restrict__ xn) {
    int gt = blockIdx.x * blockDim.x + threadIdx.x;
    int d = gt >> 5, lane = gt & 31;
    if (d >= NNODES) return;
    const int off = lane * 8;

    float4 xr0 = *(const float4*)(g_xr + (size_t)d * 256 + off);
    float4 xr1 = *(const float4*)(g_xr + (size_t)d * 256 + off + 4);
    float4 at0 = *(const float4*)(att + off);
    float4 at1 = *(const float4*)(att + off + 4);

    float acc[8];
    float denom;
    // ---- self loop: src = d, edge feature = eloop ----
    {
        float4 a0 = *(const float4*)(g_xl + (size_t)d * 256 + off);
        float4 a1 = *(const float4*)(g_xl + (size_t)d * 256 + off + 4);
        float4 e0 = *(const float4*)(g_eloop + off);
        float4 e1 = *(const float4*)(g_eloop + off + 4);
        float t = 0.0f, m;
        m = a0.x + xr0.x + e0.x; m = fmaxf(m, 0.2f * m); t = fmaf(m, at0.x, t);
        m = a0.y + xr0.y + e0.y; m = fmaxf(m, 0.2f * m); t = fmaf(m, at0.y, t);
        m = a0.z + xr0.z + e0.z; m = fmaxf(m, 0.2f * m); t = fmaf(m, at0.z, t);
        m = a0.w + xr0.w + e0.w; m = fmaxf(m, 0.2f * m); t = fmaf(m, at0.w, t);
        m = a1.x + xr1.x + e1.x; m = fmaxf(m, 0.2f * m); t = fmaf(m, at1.x, t);
        m = a1.y + xr1.y + e1.y; m = fmaxf(m, 0.2f * m); t = fmaf(m, at1.y, t);
        m = a1.z + xr1.z + e1.z; m = fmaxf(m, 0.2f * m); t = fmaf(m, at1.z, t);
        m = a1.w + xr1.w + e1.w; m = fmaxf(m, 0.2f * m); t = fmaf(m, at1.w, t);
        t += __shfl_down_sync(0xffffffffu, t, 4, 8);
        t += __shfl_down_sync(0xffffffffu, t, 2, 8);
        t += __shfl_down_sync(0xffffffffu, t, 1, 8);
        float p = __expf(__shfl_sync(0xffffffffu, t, 0, 8));
        denom = p;
        acc[0] = p * a0.x; acc[1] = p * a0.y; acc[2] = p * a0.z; acc[3] = p * a0.w;
        acc[4] = p * a1.x; acc[5] = p * a1.y; acc[6] = p * a1.z; acc[7] = p * a1.w;
    }
    // ---- real edges (dst-sorted CSR) ----
    const int beg = g_rowptr[d], end = g_rowptr[d + 1];
    for (int i = beg; i < end; i++) {
        int s = g_ssrc[i];
        int e = g_seid[i];
        float4 a0 = *(const float4*)(g_xl + (size_t)s * 256 + off);
        float4 a1 = *(const float4*)(g_xl + (size_t)s * 256 + off + 4);
        float4 e0 = *(const float4*)(g_eproj + (size_t)e * 256 + off);
        float4 e1 = *(const float4*)(g_eproj + (size_t)e * 256 + off + 4);
        float t = 0.0f, m;
        m = a0.x + xr0.x + e0.x; m = fmaxf(m, 0.2f * m); t = fmaf(m, at0.x, t);
        m = a0.y + xr0.y + e0.y; m = fmaxf(m, 0.2f * m); t = fmaf(m, at0.y, t);
        m = a0.z + xr0.z + e0.z; m = fmaxf(m, 0.2f * m); t = fmaf(m, at0.z, t);
        m = a0.w + xr0.w + e0.w; m = fmaxf(m, 0.2f * m); t = fmaf(m, at0.w, t);
        m = a1.x + xr1.x + e1.x; m = fmaxf(m, 0.2f * m); t = fmaf(m, at1.x, t);
        m = a1.y + xr1.y + e1.y; m = fmaxf(m, 0.2f * m); t = fmaf(m, at1.y, t);
        m = a1.z + xr1.z + e1.z; m = fmaxf(m, 0.2f * m); t = fmaf(m, at1.z, t);
        m = a1.w + xr1.w + e1.w; m = fmaxf(m, 0.2f * m); t = fmaf(m, at1.w, t);
        t += __shfl_down_sync(0xffffffffu, t, 4, 8);
        t += __shfl_down_sync(0xffffffffu, t, 2, 8);
        t += __shfl_down_sync(0xffffffffu, t, 1, 8);
        float p = __expf(__shfl_sync(0xffffffffu, t, 0, 8));
        denom += p;
        acc[0] = fmaf(p, a0.x, acc[0]); acc[1] = fmaf(p, a0.y, acc[1]);
        acc[2] = fmaf(p, a0.z, acc[2]); acc[3] = fmaf(p, a0.w, acc[3]);
        acc[4] = fmaf(p, a1.x, acc[4]); acc[5] = fmaf(p, a1.y, acc[5]);
        acc[6] = fmaf(p, a1.z, acc[6]); acc[7] = fmaf(p, a1.w, acc[7]);
    }
    float inv = 1.0f / (denom + 1e-16f);
    float4 b0 = *(const float4*)(bias + off);
    float4 b1 = *(const float4*)(bias + off + 4);
    float4 o0, o1;
    o0.x = fmaxf(fmaf(acc[0], inv, b0.x), 0.f); o0.y = fmaxf(fmaf(acc[1], inv, b0.y), 0.f);
    o0.z = fmaxf(fmaf(acc[2], inv, b0.z), 0.f); o0.w = fmaxf(fmaf(acc[3], inv, b0.w), 0.f);
    o1.x = fmaxf(fmaf(acc[4], inv, b1.x), 0.f); o1.y = fmaxf(fmaf(acc[5], inv, b1.y), 0.f);
    o1.z = fmaxf(fmaf(acc[6], inv, b1.z), 0.f); o1.w = fmaxf(fmaf(acc[7], inv, b1.w), 0.f);
    *(float4*)(xn + (size_t)d * 256 + off) = o0;
    *(float4*)(xn + (size_t)d * 256 + off + 4) = o1;
}

// ---------------- global mean pool ----------------
__global__ void pool_kernel(const int* __restrict__ batch, const float* __restrict__ xf) {
    int gt = blockIdx.x * blockDim.x + threadIdx.x;
    int node = gt >> 5, lane = gt & 31;
    if (node >= NNODES) return;
    int g = batch[node];
    const float4* xs = (const float4*)(xf + (size_t)node * 256) + lane * 2;
    float4 v0 = xs[0], v1 = xs[1];
    float* bp = g_gsum + (size_t)g * 256 + lane * 8;
    red4(bp,     v0.x, v0.y, v0.z, v0.w);
    red4(bp + 4, v1.x, v1.y, v1.z, v1.w);
    if (lane == 0) atomicAdd(&g_gcnt[g], 1.0f);
}

// ---------------- final MLP ----------------
__global__ __launch_bounds__(128)
void mlp_kernel(const float* __restrict__ Wp1, const float* __restrict__ bp1,
                const float* __restrict__ Wp2, const float* __restrict__ bp2,
                float* __restrict__ out) {
    int g = blockIdx.x;
    __shared__ float pooled[256];
    __shared__ float partial[4];
    float cnt = fmaxf(g_gcnt[g], 1.0f);
    for (int i = threadIdx.x; i < 256; i += 128)
        pooled[i] = g_gsum[(size_t)g * 256 + i] / cnt;
    __syncthreads();
    int j = threadIdx.x;
    float acc = bp1[j];
#pragma unroll 8
    for (int k = 0; k < 256; k++) acc = fmaf(pooled[k], Wp1[k * 128 + j], acc);
    float h = fmaxf(acc, 0.0f) * Wp2[j];
#pragma unroll
    for (int o = 16; o; o >>= 1) h += __shfl_down_sync(0xffffffffu, h, o);
    if ((threadIdx.x & 31) == 0) partial[threadIdx.x >> 5] = h;
    __syncthreads();
    if (threadIdx.x == 0)
        out[g] = partial[0] + partial[1] + partial[2] + partial[3] + bp2[0];
}

// ---------------- launcher ----------------
extern "C" void kernel_launch(void* const* d_in, const int* in_sizes, int n_in,
                              void* d_out, int out_size) {
    const float* x     = (const float*)d_in[0];
    const int*   ei    = (const int*)  d_in[1];
    const float* ea    = (const float*)d_in[2];
    const int*   batch = (const int*)  d_in[3];
    const float* Wl    = (const float*)d_in[4];
    const float* bl    = (const float*)d_in[5];
    const float* Wr    = (const float*)d_in[6];
    const float* br    = (const float*)d_in[7];
    const float* We    = (const float*)d_in[8];
    const float* att   = (const float*)d_in[9];
    const float* bias  = (const float*)d_in[10];
    const float* Wp1   = (const float*)d_in[11];
    const float* bp1   = (const float*)d_in[12];
    const float* Wp2   = (const float*)d_in[13];
    const float* bp2   = (const float*)d_in[14];
    float* out = (float*)d_out;
    const int* src = ei;
    const int* dst = ei + NEDGES;

    float *bufA, *bufB, *xl, *xr, *eproj, *esum, *gsum, *gcnt;
    int* cnt;
    cudaGetSymbolAddress((void**)&bufA,  g_bufA);
    cudaGetSymbolAddress((void**)&bufB,  g_bufB);
    cudaGetSymbolAddress((void**)&xl,    g_xl);
    cudaGetSymbolAddress((void**)&xr,    g_xr);
    cudaGetSymbolAddress((void**)&eproj, g_eproj);
    cudaGetSymbolAddress((void**)&esum,  g_esum);
    cudaGetSymbolAddress((void**)&gsum,  g_gsum);
    cudaGetSymbolAddress((void**)&gcnt,  g_gcnt);
    cudaGetSymbolAddress((void**)&cnt,   g_cnt);

    // ---- CSR build (graph topology is constant) ----
    cudaMemsetAsync(cnt, 0, NNODES * sizeof(int));
    hist_kernel<<<(NEDGES + 255) / 256, 256>>>(dst);
    blocksum_kernel<<<NBLK, 256>>>();
    scanb_kernel<<<1, 512>>>();
    rowptr_kernel<<<NBLK, 256>>>();
    fill_kernel<<<(NEDGES + 255) / 256, 256>>>(src, dst);

    cudaMemsetAsync(esum, 0, EDIM * sizeof(float));
    esum_kernel<<<512, 256>>>(ea);

    const float* xcur = x;
    for (int l = 0; l < NLAYER; l++) {
        float* xn = (l & 1) ? bufB : bufA;
        dim3 gN((NNODES + 127) / 128, 2);
        gemm_mma<256, true><<<gN, 256>>>(xcur, Wl + (size_t)l * 256 * 256, bl + l * 256, xl, NNODES);
        gemm_mma<256, true><<<gN, 256>>>(xcur, Wr + (size_t)l * 256 * 256, br + l * 256, xr, NNODES);
        dim3 gE((NEDGES + 127) / 128, 2);
        gemm_mma<64, false><<<gE, 256>>>(ea, We + (size_t)l * 64 * 256, nullptr, eproj, NEDGES);
        eloop_kernel<<<1, 256>>>(We + (size_t)l * 64 * 256);

        fused_gat_kernel<<<(NNODES * 32 + 255) / 256, 256>>>(att + l * 256, bias + l * 256, xn);
        xcur = xn;
    }

    cudaMemsetAsync(gsum, 0, (size_t)GDIM * 256 * sizeof(float));
    cudaMemsetAsync(gcnt, 0, GDIM * sizeof(float));
    pool_kernel<<<(NNODES * 32 + 255) / 256, 256>>>(batch, xcur);
    mlp_kernel<<<GDIM, 128>>>(Wp1, bp1, Wp2, bp2, out);
}

// round 7
// speedup vs baseline: 1.1342x; 1.0422x over previous
#include <cuda_runtime.h>
#include <cuda_bf16.h>
#include <cstdint>

#define NNODES 100000
#define NEDGES 300000
#define GDIM   2048
#define HIDDIM 256
#define EDIM   64
#define NLAYER 3
#define NBLK   ((NNODES + 255) / 256)   // 391

// ---------------- static device scratch ----------------
__device__ float g_bufA[(size_t)NNODES * HIDDIM];
__device__ float g_bufB[(size_t)NNODES * HIDDIM];
__device__ float g_xl[(size_t)NNODES * HIDDIM];
__device__ float g_xr[(size_t)NNODES * HIDDIM];
__device__ __nv_bfloat16 g_eproj[(size_t)NEDGES * HIDDIM];  // bf16, CSR-sorted order
__device__ float g_easorted[(size_t)NEDGES * EDIM];         // edge_attr in CSR order
__device__ float g_eloop[HIDDIM];
__device__ float g_esum[EDIM];
__device__ float g_gsum[(size_t)GDIM * HIDDIM];
__device__ float g_gcnt[GDIM];
// CSR (dst-sorted edges)
__device__ int g_cnt[NNODES];
__device__ int g_bsum[512];
__device__ int g_rowptr[NNODES + 1];
__device__ int g_woff[NNODES];
__device__ int g_ssrc[NEDGES];
__device__ int g_seid[NEDGES];

// ---------------- helpers ----------------
__device__ __forceinline__ void red4(float* p, float a, float b, float c, float d) {
    asm volatile("red.global.add.v4.f32 [%0], {%1,%2,%3,%4};"
                 :: "l"(p), "f"(a), "f"(b), "f"(c), "f"(d) : "memory");
}
__device__ __forceinline__ void mma_tf32(float* c, const uint32_t* a, const uint32_t* b) {
    asm volatile("mma.sync.aligned.m16n8k8.row.col.f32.tf32.tf32.f32 "
                 "{%0,%1,%2,%3}, {%4,%5,%6,%7}, {%8,%9}, {%0,%1,%2,%3};"
                 : "+f"(c[0]), "+f"(c[1]), "+f"(c[2]), "+f"(c[3])
                 : "r"(a[0]), "r"(a[1]), "r"(a[2]), "r"(a[3]), "r"(b[0]), "r"(b[1]));
}

// ================= GEMM core macro-body (CTA 128x128, BK=32, 8 warps 4x2) =================
// Computes acc[2][8][4] for C-tile at (row0, col0) from A[M,K] and W[K,256].
#define GEMM_BODY(A, W, K, M, row0, col0)                                            \
    float acc[2][8][4];                                                              \
    _Pragma("unroll") for (int mt = 0; mt < 2; mt++)                                 \
    _Pragma("unroll") for (int nt = 0; nt < 8; nt++)                                 \
    _Pragma("unroll") for (int i = 0; i < 4; i++) acc[mt][nt][i] = 0.0f;             \
    float4 pa[4], pb[4];                                                             \
    _Pragma("unroll") for (int i = 0; i < 4; i++) {                                  \
        int idx = tid + i * 256;                                                     \
        int r = idx >> 3, q = idx & 7;                                               \
        int ar = row0 + r; if (ar >= M) ar = M - 1;                                  \
        pa[i] = *(const float4*)(A + (size_t)ar * K + q * 4);                        \
        int rb = idx >> 5, qb = idx & 31;                                            \
        pb[i] = *(const float4*)(W + (size_t)rb * 256 + col0 + qb * 4);              \
    }                                                                                \
    for (int k0 = 0; k0 < K; k0 += 32) {                                             \
        _Pragma("unroll") for (int i = 0; i < 4; i++) {                              \
            int idx = tid + i * 256;                                                 \
            int r = idx >> 3, q = idx & 7;                                           \
            *(float4*)&As[r][q * 4] = pa[i];                                         \
            int rb = idx >> 5, qb = idx & 31;                                        \
            *(float4*)&Bs[rb][qb * 4] = pb[i];                                       \
        }                                                                            \
        __syncthreads();                                                             \
        if (k0 + 32 < K) {                                                           \
            _Pragma("unroll") for (int i = 0; i < 4; i++) {                          \
                int idx = tid + i * 256;                                             \
                int r = idx >> 3, q = idx & 7;                                       \
                int ar = row0 + r; if (ar >= M) ar = M - 1;                          \
                pa[i] = *(const float4*)(A + (size_t)ar * K + k0 + 32 + q * 4);      \
                int rb = idx >> 5, qb = idx & 31;                                    \
                pb[i] = *(const float4*)(W + (size_t)(k0 + 32 + rb) * 256 + col0 + qb * 4); \
            }                                                                        \
        }                                                                            \
        _Pragma("unroll") for (int ks = 0; ks < 4; ks++) {                           \
            const int kb = ks * 8;                                                   \
            uint32_t bf[8][2];                                                       \
            const int brow = kb + lr, bcol = warp_n * 64 + lq;                       \
            _Pragma("unroll") for (int nt = 0; nt < 8; nt++) {                       \
                bf[nt][0] = __float_as_uint(Bs[brow][bcol + nt * 8]);                \
                bf[nt][1] = __float_as_uint(Bs[brow + 4][bcol + nt * 8]);            \
            }                                                                        \
            _Pragma("unroll") for (int mt = 0; mt < 2; mt++) {                       \
                uint32_t af[4];                                                      \
                const int arow = warp_m * 32 + mt * 16 + lq;                         \
                af[0] = __float_as_uint(As[arow][kb + lr]);                          \
                af[1] = __float_as_uint(As[arow + 8][kb + lr]);                      \
                af[2] = __float_as_uint(As[arow][kb + 4 + lr]);                      \
                af[3] = __float_as_uint(As[arow + 8][kb + 4 + lr]);                  \
                _Pragma("unroll") for (int nt = 0; nt < 8; nt++)                     \
                    mma_tf32(acc[mt][nt], af, bf[nt]);                               \
            }                                                                        \
        }                                                                            \
        __syncthreads();                                                             \
    }

// ---------------- fused node GEMM: xl = A@Wl+bl, xr = A@Wr+br in one kernel ----------------
// grid.y: 0,1 -> Wl cols 0/128 ; 2,3 -> Wr cols 0/128. All col-blocks of same rows
// run concurrently -> A fetched from DRAM once.
__global__ __launch_bounds__(256)
void gemm_node(const float* __restrict__ A,
               const float* __restrict__ Wl_, const float* __restrict__ Wr_,
               const float* __restrict__ bl_, const float* __restrict__ br_,
               float* __restrict__ Cl, float* __restrict__ Cr, int M) {
    __shared__ __align__(16) float As[128][36];
    __shared__ __align__(16) float Bs[32][136];
    const int tid = threadIdx.x, warp = tid >> 5, lane = tid & 31;
    const int warp_m = warp & 3, warp_n = warp >> 2;
    const int row0 = blockIdx.x * 128;
    const int col0 = (blockIdx.y & 1) * 128;
    const float* W    = (blockIdx.y < 2) ? Wl_ : Wr_;
    const float* bias = (blockIdx.y < 2) ? bl_ : br_;
    float* C          = (blockIdx.y < 2) ? Cl  : Cr;
    const int lq = lane >> 2, lr = lane & 3;

    GEMM_BODY(A, W, 256, M, row0, col0)

    const int r_base = row0 + warp_m * 32 + lq;
    const int c_base = col0 + warp_n * 64 + lr * 2;
#pragma unroll
    for (int nt = 0; nt < 8; nt++) {
        int c = c_base + nt * 8;
        float2 bv = *(const float2*)(bias + c);
#pragma unroll
        for (int mt = 0; mt < 2; mt++) {
            int r = r_base + mt * 16;
            if (r < M) {
                float2 o0 = make_float2(acc[mt][nt][0] + bv.x, acc[mt][nt][1] + bv.y);
                *(float2*)(C + (size_t)r * 256 + c) = o0;
            }
            if (r + 8 < M) {
                float2 o1 = make_float2(acc[mt][nt][2] + bv.x, acc[mt][nt][3] + bv.y);
                *(float2*)(C + (size_t)(r + 8) * 256 + c) = o1;
            }
        }
    }
}

// ---------------- edge GEMM: eproj_bf16[i] = (easorted @ We)[i], CSR row order ----------------
__global__ __launch_bounds__(256)
void gemm_edge(const float* __restrict__ W) {
    __shared__ __align__(16) float As[128][36];
    __shared__ __align__(16) float Bs[32][136];
    const float* A = g_easorted;
    const int tid = threadIdx.x, warp = tid >> 5, lane = tid & 31;
    const int warp_m = warp & 3, warp_n = warp >> 2;
    const int row0 = blockIdx.x * 128;
    const int col0 = blockIdx.y * 128;
    const int lq = lane >> 2, lr = lane & 3;
    const int M = NEDGES;

    GEMM_BODY(A, W, 64, M, row0, col0)

    const int r_base = row0 + warp_m * 32 + lq;
    const int c_base = col0 + warp_n * 64 + lr * 2;
#pragma unroll
    for (int nt = 0; nt < 8; nt++) {
        int c = c_base + nt * 8;
#pragma unroll
        for (int mt = 0; mt < 2; mt++) {
            int r = r_base + mt * 16;
            if (r < M) {
                __nv_bfloat162 v = __floats2bfloat162_rn(acc[mt][nt][0], acc[mt][nt][1]);
                *(__nv_bfloat162*)(g_eproj + (size_t)r * 256 + c) = v;
            }
            if (r + 8 < M) {
                __nv_bfloat162 v = __floats2bfloat162_rn(acc[mt][nt][2], acc[mt][nt][3]);
                *(__nv_bfloat162*)(g_eproj + (size_t)(r + 8) * 256 + c) = v;
            }
        }
    }
}

// ---------------- CSR build (once per launch) ----------------
__global__ void hist_kernel(const int* __restrict__ dst) {
    int e = blockIdx.x * blockDim.x + threadIdx.x;
    if (e < NEDGES) atomicAdd(&g_cnt[dst[e]], 1);
}
__global__ void blocksum_kernel() {
    int i = blockIdx.x * 256 + threadIdx.x;
    int v = (i < NNODES) ? g_cnt[i] : 0;
    __shared__ int ws[8];
#pragma unroll
    for (int o = 16; o; o >>= 1) v += __shfl_down_sync(0xffffffffu, v, o);
    if ((threadIdx.x & 31) == 0) ws[threadIdx.x >> 5] = v;
    __syncthreads();
    if (threadIdx.x == 0) {
        int s = 0;
#pragma unroll
        for (int j = 0; j < 8; j++) s += ws[j];
        g_bsum[blockIdx.x] = s;
    }
}
__global__ void scanb_kernel() {
    __shared__ int sm[512];
    int i = threadIdx.x;
    int v = (i < NBLK) ? g_bsum[i] : 0;
    sm[i] = v;
    __syncthreads();
    for (int s = 1; s < 512; s <<= 1) {
        int t = (i >= s) ? sm[i - s] : 0;
        __syncthreads();
        sm[i] += t;
        __syncthreads();
    }
    if (i < NBLK) g_bsum[i] = sm[i] - v;
}
__global__ void rowptr_kernel() {
    int tid = threadIdx.x;
    int i = blockIdx.x * 256 + tid;
    int v = (i < NNODES) ? g_cnt[i] : 0;
    __shared__ int sm[256];
    sm[tid] = v;
    __syncthreads();
    for (int s = 1; s < 256; s <<= 1) {
        int t = (tid >= s) ? sm[tid - s] : 0;
        __syncthreads();
        sm[tid] += t;
        __syncthreads();
    }
    int ex = sm[tid] - v + g_bsum[blockIdx.x];
    if (i < NNODES) { g_rowptr[i] = ex; g_woff[i] = ex; }
    if (i == NNODES - 1) g_rowptr[NNODES] = NEDGES;
}
__global__ void fill_kernel(const int* __restrict__ src, const int* __restrict__ dst) {
    int e = blockIdx.x * blockDim.x + threadIdx.x;
    if (e >= NEDGES) return;
    int d = dst[e];
    int pos = atomicAdd(&g_woff[d], 1);
    g_ssrc[pos] = src[e];
    g_seid[pos] = e;
}
// permute edge_attr into dst-sorted order
__global__ void permute_ea_kernel(const float* __restrict__ ea) {
    int gt = blockIdx.x * blockDim.x + threadIdx.x;   // over NEDGES*16 float4s
    if (gt >= NEDGES * 16) return;
    int i = gt >> 4, q = gt & 15;
    int e = g_seid[i];
    ((float4*)g_easorted)[(size_t)i * 16 + q] = ((const float4*)ea)[(size_t)e * 16 + q];
}

// ---------------- edge_attr column sums (once) ----------------
__global__ void esum_kernel(const float* __restrict__ ea) {
    int col = threadIdx.x & 63;
    int rowsPerBlk = blockDim.x >> 6;
    int r0 = blockIdx.x * rowsPerBlk + (threadIdx.x >> 6);
    int rstride = gridDim.x * rowsPerBlk;
    float s = 0.0f;
    for (int r = r0; r < NEDGES; r += rstride) s += ea[(size_t)r * EDIM + col];
    atomicAdd(&g_esum[col], s);
}
__global__ void eloop_kernel(const float* __restrict__ We) {
    int j = threadIdx.x;
    const float inv = 1.0f / (float)NEDGES;
    float acc = 0.0f;
#pragma unroll
    for (int k = 0; k < EDIM; k++) acc = fmaf(g_esum[k] * inv, We[k * 256 + j], acc);
    g_eloop[j] = acc;
}

// ---------------- fused GAT edge phase: warp per dst node ----------------
__global__ __launch_bounds__(256)
void fused_gat_kernel(const float* __restrict__ att, const float* __restrict__ bias,
                      float* __restrict__ xn) {
    int gt = blockIdx.x * blockDim.x + threadIdx.x;
    int d = gt >> 5, lane = gt & 31;
    if (d >= NNODES) return;
    const int off = lane * 8;

    float4 xr0 = *(const float4*)(g_xr + (size_t)d * 256 + off);
    float4 xr1 = *(const float4*)(g_xr + (size_t)d * 256 + off + 4);
    float4 at0 = *(const float4*)(att + off);
    float4 at1 = *(const float4*)(att + off + 4);

    float acc[8];
    float denom;
    // ---- self loop: src = d, edge feature = eloop (fp32) ----
    {
        float4 a0 = *(const float4*)(g_xl + (size_t)d * 256 + off);
        float4 a1 = *(const float4*)(g_xl + (size_t)d * 256 + off + 4);
        float4 e0 = *(const float4*)(g_eloop + off);
        float4 e1 = *(const float4*)(g_eloop + off + 4);
        float t = 0.0f, m;
        m = a0.x + xr0.x + e0.x; m = fmaxf(m, 0.2f * m); t = fmaf(m, at0.x, t);
        m = a0.y + xr0.y + e0.y; m = fmaxf(m, 0.2f * m); t = fmaf(m, at0.y, t);
        m = a0.z + xr0.z + e0.z; m = fmaxf(m, 0.2f * m); t = fmaf(m, at0.z, t);
        m = a0.w + xr0.w + e0.w; m = fmaxf(m, 0.2f * m); t = fmaf(m, at0.w, t);
        m = a1.x + xr1.x + e1.x; m = fmaxf(m, 0.2f * m); t = fmaf(m, at1.x, t);
        m = a1.y + xr1.y + e1.y; m = fmaxf(m, 0.2f * m); t = fmaf(m, at1.y, t);
        m = a1.z + xr1.z + e1.z; m = fmaxf(m, 0.2f * m); t = fmaf(m, at1.z, t);
        m = a1.w + xr1.w + e1.w; m = fmaxf(m, 0.2f * m); t = fmaf(m, at1.w, t);
        t += __shfl_down_sync(0xffffffffu, t, 4, 8);
        t += __shfl_down_sync(0xffffffffu, t, 2, 8);
        t += __shfl_down_sync(0xffffffffu, t, 1, 8);
        float p = __expf(__shfl_sync(0xffffffffu, t, 0, 8));
        denom = p;
        acc[0] = p * a0.x; acc[1] = p * a0.y; acc[2] = p * a0.z; acc[3] = p * a0.w;
        acc[4] = p * a1.x; acc[5] = p * a1.y; acc[6] = p * a1.z; acc[7] = p * a1.w;
    }
    // ---- real edges: CSR order, eproj sequential bf16 ----
    const int beg = g_rowptr[d], end = g_rowptr[d + 1];
    for (int i = beg; i < end; i++) {
        int s = g_ssrc[i];
        float4 a0 = *(const float4*)(g_xl + (size_t)s * 256 + off);
        float4 a1 = *(const float4*)(g_xl + (size_t)s * 256 + off + 4);
        uint4 eu = *((const uint4*)(g_eproj + (size_t)i * 256) + lane);
        float2 f0 = __bfloat1622float2(*(__nv_bfloat162*)&eu.x);
        float2 f1 = __bfloat1622float2(*(__nv_bfloat162*)&eu.y);
        float2 f2 = __bfloat1622float2(*(__nv_bfloat162*)&eu.z);
        float2 f3 = __bfloat1622float2(*(__nv_bfloat162*)&eu.w);
        float t = 0.0f, m;
        m = a0.x + xr0.x + f0.x; m = fmaxf(m, 0.2f * m); t = fmaf(m, at0.x, t);
        m = a0.y + xr0.y + f0.y; m = fmaxf(m, 0.2f * m); t = fmaf(m, at0.y, t);
        m = a0.z + xr0.z + f1.x; m = fmaxf(m, 0.2f * m); t = fmaf(m, at0.z, t);
        m = a0.w + xr0.w + f1.y; m = fmaxf(m, 0.2f * m); t = fmaf(m, at0.w, t);
        m = a1.x + xr1.x + f2.x; m = fmaxf(m, 0.2f * m); t = fmaf(m, at1.x, t);
        m = a1.y + xr1.y + f2.y; m = fmaxf(m, 0.2f * m); t = fmaf(m, at1.y, t);
        m = a1.z + xr1.z + f3.x; m = fmaxf(m, 0.2f * m); t = fmaf(m, at1.z, t);
        m = a1.w + xr1.w + f3.y; m = fmaxf(m, 0.2f * m); t = fmaf(m, at1.w, t);
        t += __shfl_down_sync(0xffffffffu, t, 4, 8);
        t += __shfl_down_sync(0xffffffffu, t, 2, 8);
        t += __shfl_down_sync(0xffffffffu, t, 1, 8);
        float p = __expf(__shfl_sync(0xffffffffu, t, 0, 8));
        denom += p;
        acc[0] = fmaf(p, a0.x, acc[0]); acc[1] = fmaf(p, a0.y, acc[1]);
        acc[2] = fmaf(p, a0.z, acc[2]); acc[3] = fmaf(p, a0.w, acc[3]);
        acc[4] = fmaf(p, a1.x, acc[4]); acc[5] = fmaf(p, a1.y, acc[5]);
        acc[6] = fmaf(p, a1.z, acc[6]); acc[7] = fmaf(p, a1.w, acc[7]);
    }
    float inv = 1.0f / (denom + 1e-16f);
    float4 b0 = *(const float4*)(bias + off);
    float4 b1 = *(const float4*)(bias + off + 4);
    float4 o0, o1;
    o0.x = fmaxf(fmaf(acc[0], inv, b0.x), 0.f); o0.y = fmaxf(fmaf(acc[1], inv, b0.y), 0.f);
    o0.z = fmaxf(fmaf(acc[2], inv, b0.z), 0.f); o0.w = fmaxf(fmaf(acc[3], inv, b0.w), 0.f);
    o1.x = fmaxf(fmaf(acc[4], inv, b1.x), 0.f); o1.y = fmaxf(fmaf(acc[5], inv, b1.y), 0.f);
    o1.z = fmaxf(fmaf(acc[6], inv, b1.z), 0.f); o1.w = fmaxf(fmaf(acc[7], inv, b1.w), 0.f);
    *(float4*)(xn + (size_t)d * 256 + off) = o0;
    *(float4*)(xn + (size_t)d * 256 + off + 4) = o1;
}

// ---------------- global mean pool ----------------
__global__ void pool_kernel(const int* __restrict__ batch, const float* __restrict__ xf) {
    int gt = blockIdx.x * blockDim.x + threadIdx.x;
    int node = gt >> 5, lane = gt & 31;
    if (node >= NNODES) return;
    int g = batch[node];
    const float4* xs = (const float4*)(xf + (size_t)node * 256) + lane * 2;
    float4 v0 = xs[0], v1 = xs[1];
    float* bp = g_gsum + (size_t)g * 256 + lane * 8;
    red4(bp,     v0.x, v0.y, v0.z, v0.w);
    red4(bp + 4, v1.x, v1.y, v1.z, v1.w);
    if (lane == 0) atomicAdd(&g_gcnt[g], 1.0f);
}

// ---------------- final MLP ----------------
__global__ __launch_bounds__(128)
void mlp_kernel(const float* __restrict__ Wp1, const float* __restrict__ bp1,
                const float* __restrict__ Wp2, const float* __restrict__ bp2,
                float* __restrict__ out) {
    int g = blockIdx.x;
    __shared__ float pooled[256];
    __shared__ float partial[4];
    float cnt = fmaxf(g_gcnt[g], 1.0f);
    for (int i = threadIdx.x; i < 256; i += 128)
        pooled[i] = g_gsum[(size_t)g * 256 + i] / cnt;
    __syncthreads();
    int j = threadIdx.x;
    float acc = bp1[j];
#pragma unroll 8
    for (int k = 0; k < 256; k++) acc = fmaf(pooled[k], Wp1[k * 128 + j], acc);
    float h = fmaxf(acc, 0.0f) * Wp2[j];
#pragma unroll
    for (int o = 16; o; o >>= 1) h += __shfl_down_sync(0xffffffffu, h, o);
    if ((threadIdx.x & 31) == 0) partial[threadIdx.x >> 5] = h;
    __syncthreads();
    if (threadIdx.x == 0)
        out[g] = partial[0] + partial[1] + partial[2] + partial[3] + bp2[0];
}

// ---------------- launcher ----------------
extern "C" void kernel_launch(void* const* d_in, const int* in_sizes, int n_in,
                              void* d_out, int out_size) {
    const float* x     = (const float*)d_in[0];
    const int*   ei    = (const int*)  d_in[1];
    const float* ea    = (const float*)d_in[2];
    const int*   batch = (const int*)  d_in[3];
    const float* Wl    = (const float*)d_in[4];
    const float* bl    = (const float*)d_in[5];
    const float* Wr    = (const float*)d_in[6];
    const float* br    = (const float*)d_in[7];
    const float* We    = (const float*)d_in[8];
    const float* att   = (const float*)d_in[9];
    const float* bias  = (const float*)d_in[10];
    const float* Wp1   = (const float*)d_in[11];
    const float* bp1   = (const float*)d_in[12];
    const float* Wp2   = (const float*)d_in[13];
    const float* bp2   = (const float*)d_in[14];
    float* out = (float*)d_out;
    const int* src = ei;
    const int* dst = ei + NEDGES;

    float *bufA, *bufB, *xl, *xr, *esum, *gsum, *gcnt;
    int* cnt;
    cudaGetSymbolAddress((void**)&bufA,  g_bufA);
    cudaGetSymbolAddress((void**)&bufB,  g_bufB);
    cudaGetSymbolAddress((void**)&xl,    g_xl);
    cudaGetSymbolAddress((void**)&xr,    g_xr);
    cudaGetSymbolAddress((void**)&esum,  g_esum);
    cudaGetSymbolAddress((void**)&gsum,  g_gsum);
    cudaGetSymbolAddress((void**)&gcnt,  g_gcnt);
    cudaGetSymbolAddress((void**)&cnt,   g_cnt);

    // ---- CSR build + ea permutation (topology constant) ----
    cudaMemsetAsync(cnt, 0, NNODES * sizeof(int));
    hist_kernel<<<(NEDGES + 255) / 256, 256>>>(dst);
    blocksum_kernel<<<NBLK, 256>>>();
    scanb_kernel<<<1, 512>>>();
    rowptr_kernel<<<NBLK, 256>>>();
    fill_kernel<<<(NEDGES + 255) / 256, 256>>>(src, dst);
    permute_ea_kernel<<<(NEDGES * 16 + 255) / 256, 256>>>(ea);

    cudaMemsetAsync(esum, 0, EDIM * sizeof(float));
    esum_kernel<<<512, 256>>>(ea);

    const float* xcur = x;
    for (int l = 0; l < NLAYER; l++) {
        float* xn = (l & 1) ? bufB : bufA;
        dim3 gN((NNODES + 127) / 128, 4);
        gemm_node<<<gN, 256>>>(xcur, Wl + (size_t)l * 256 * 256, Wr + (size_t)l * 256 * 256,
                               bl + l * 256, br + l * 256, xl, xr, NNODES);
        dim3 gE((NEDGES + 127) / 128, 2);
        gemm_edge<<<gE, 256>>>(We + (size_t)l * 64 * 256);
        eloop_kernel<<<1, 256>>>(We + (size_t)l * 64 * 256);

        fused_gat_kernel<<<(NNODES * 32 + 255) / 256, 256>>>(att + l * 256, bias + l * 256, xn);
        xcur = xn;
    }

    cudaMemsetAsync(gsum, 0, (size_t)GDIM * 256 * sizeof(float));
    cudaMemsetAsync(gcnt, 0, GDIM * sizeof(float));
    pool_kernel<<<(NNODES * 32 + 255) / 256, 256>>>(batch, xcur);
    mlp_kernel<<<GDIM, 128>>>(Wp1, bp1, Wp2, bp2, out);
}

// round 8
// speedup vs baseline: 1.1977x; 1.0559x over previous
#include <cuda_runtime.h>
#include <cuda_bf16.h>
#include <cstdint>

#define NNODES 100000
#define NEDGES 300000
#define GDIM   2048
#define HIDDIM 256
#define EDIM   64
#define NLAYER 3
#define NBLK   ((NNODES + 255) / 256)   // 391

// ---------------- static device scratch ----------------
__device__ float g_bufA[(size_t)NNODES * HIDDIM];
__device__ float g_bufB[(size_t)NNODES * HIDDIM];
__device__ __nv_bfloat16 g_xl[(size_t)NNODES * HIDDIM];    // bf16 node features (src side)
__device__ __nv_bfloat16 g_xr[(size_t)NNODES * HIDDIM];    // bf16 node features (dst side)
__device__ __nv_bfloat16 g_eproj[(size_t)NEDGES * HIDDIM]; // bf16, CSR-sorted order
__device__ float g_easorted[(size_t)NEDGES * EDIM];        // edge_attr in CSR order
__device__ float g_eloop[HIDDIM];
__device__ float g_esum[EDIM];
__device__ float g_gsum[(size_t)GDIM * HIDDIM];
__device__ float g_gcnt[GDIM];
// CSR (dst-sorted edges)
__device__ int g_cnt[NNODES];
__device__ int g_bsum[512];
__device__ int g_rowptr[NNODES + 1];
__device__ int g_woff[NNODES];
__device__ int g_ssrc[NEDGES];
__device__ int g_seid[NEDGES];

// ---------------- helpers ----------------
__device__ __forceinline__ void red4(float* p, float a, float b, float c, float d) {
    asm volatile("red.global.add.v4.f32 [%0], {%1,%2,%3,%4};"
                 :: "l"(p), "f"(a), "f"(b), "f"(c), "f"(d) : "memory");
}
__device__ __forceinline__ void mma_tf32(float* c, const uint32_t* a, const uint32_t* b) {
    asm volatile("mma.sync.aligned.m16n8k8.row.col.f32.tf32.tf32.f32 "
                 "{%0,%1,%2,%3}, {%4,%5,%6,%7}, {%8,%9}, {%0,%1,%2,%3};"
                 : "+f"(c[0]), "+f"(c[1]), "+f"(c[2]), "+f"(c[3])
                 : "r"(a[0]), "r"(a[1]), "r"(a[2]), "r"(a[3]), "r"(b[0]), "r"(b[1]));
}
// load 8 consecutive bf16 (16B) and expand to two float4
__device__ __forceinline__ void ld8bf16(const __nv_bfloat16* p, float4& o0, float4& o1) {
    uint4 u = *(const uint4*)p;
    float2 f0 = __bfloat1622float2(*(__nv_bfloat162*)&u.x);
    float2 f1 = __bfloat1622float2(*(__nv_bfloat162*)&u.y);
    float2 f2 = __bfloat1622float2(*(__nv_bfloat162*)&u.z);
    float2 f3 = __bfloat1622float2(*(__nv_bfloat162*)&u.w);
    o0 = make_float4(f0.x, f0.y, f1.x, f1.y);
    o1 = make_float4(f2.x, f2.y, f3.x, f3.y);
}

// ================= GEMM core macro-body (CTA 128x128, BK=32, 8 warps 4x2) =================
#define GEMM_BODY(A, W, K, M, row0, col0)                                            \
    float acc[2][8][4];                                                              \
    _Pragma("unroll") for (int mt = 0; mt < 2; mt++)                                 \
    _Pragma("unroll") for (int nt = 0; nt < 8; nt++)                                 \
    _Pragma("unroll") for (int i = 0; i < 4; i++) acc[mt][nt][i] = 0.0f;             \
    float4 pa[4], pb[4];                                                             \
    _Pragma("unroll") for (int i = 0; i < 4; i++) {                                  \
        int idx = tid + i * 256;                                                     \
        int r = idx >> 3, q = idx & 7;                                               \
        int ar = row0 + r; if (ar >= M) ar = M - 1;                                  \
        pa[i] = *(const float4*)(A + (size_t)ar * K + q * 4);                        \
        int rb = idx >> 5, qb = idx & 31;                                            \
        pb[i] = *(const float4*)(W + (size_t)rb * 256 + col0 + qb * 4);              \
    }                                                                                \
    for (int k0 = 0; k0 < K; k0 += 32) {                                             \
        _Pragma("unroll") for (int i = 0; i < 4; i++) {                              \
            int idx = tid + i * 256;                                                 \
            int r = idx >> 3, q = idx & 7;                                           \
            *(float4*)&As[r][q * 4] = pa[i];                                         \
            int rb = idx >> 5, qb = idx & 31;                                        \
            *(float4*)&Bs[rb][qb * 4] = pb[i];                                       \
        }                                                                            \
        __syncthreads();                                                             \
        if (k0 + 32 < K) {                                                           \
            _Pragma("unroll") for (int i = 0; i < 4; i++) {                          \
                int idx = tid + i * 256;                                             \
                int r = idx >> 3, q = idx & 7;                                       \
                int ar = row0 + r; if (ar >= M) ar = M - 1;                          \
                pa[i] = *(const float4*)(A + (size_t)ar * K + k0 + 32 + q * 4);      \
                int rb = idx >> 5, qb = idx & 31;                                    \
                pb[i] = *(const float4*)(W + (size_t)(k0 + 32 + rb) * 256 + col0 + qb * 4); \
            }                                                                        \
        }                                                                            \
        _Pragma("unroll") for (int ks = 0; ks < 4; ks++) {                           \
            const int kb = ks * 8;                                                   \
            uint32_t bf[8][2];                                                       \
            const int brow = kb + lr, bcol = warp_n * 64 + lq;                       \
            _Pragma("unroll") for (int nt = 0; nt < 8; nt++) {                       \
                bf[nt][0] = __float_as_uint(Bs[brow][bcol + nt * 8]);                \
                bf[nt][1] = __float_as_uint(Bs[brow + 4][bcol + nt * 8]);            \
            }                                                                        \
            _Pragma("unroll") for (int mt = 0; mt < 2; mt++) {                       \
                uint32_t af[4];                                                      \
                const int arow = warp_m * 32 + mt * 16 + lq;                         \
                af[0] = __float_as_uint(As[arow][kb + lr]);                          \
                af[1] = __float_as_uint(As[arow + 8][kb + lr]);                      \
                af[2] = __float_as_uint(As[arow][kb + 4 + lr]);                      \
                af[3] = __float_as_uint(As[arow + 8][kb + 4 + lr]);                  \
                _Pragma("unroll") for (int nt = 0; nt < 8; nt++)                     \
                    mma_tf32(acc[mt][nt], af, bf[nt]);                               \
            }                                                                        \
        }                                                                            \
        __syncthreads();                                                             \
    }

// ---------------- fused node GEMM: xl = A@Wl+bl, xr = A@Wr+br (bf16 out) ----------------
__global__ __launch_bounds__(256)
void gemm_node(const float* __restrict__ A,
               const float* __restrict__ Wl_, const float* __restrict__ Wr_,
               const float* __restrict__ bl_, const float* __restrict__ br_,
               __nv_bfloat16* __restrict__ Cl, __nv_bfloat16* __restrict__ Cr, int M) {
    __shared__ __align__(16) float As[128][36];
    __shared__ __align__(16) float Bs[32][136];
    const int tid = threadIdx.x, warp = tid >> 5, lane = tid & 31;
    const int warp_m = warp & 3, warp_n = warp >> 2;
    const int row0 = blockIdx.x * 128;
    const int col0 = (blockIdx.y & 1) * 128;
    const float* W    = (blockIdx.y < 2) ? Wl_ : Wr_;
    const float* bias = (blockIdx.y < 2) ? bl_ : br_;
    __nv_bfloat16* C  = (blockIdx.y < 2) ? Cl  : Cr;
    const int lq = lane >> 2, lr = lane & 3;

    GEMM_BODY(A, W, 256, M, row0, col0)

    const int r_base = row0 + warp_m * 32 + lq;
    const int c_base = col0 + warp_n * 64 + lr * 2;
#pragma unroll
    for (int nt = 0; nt < 8; nt++) {
        int c = c_base + nt * 8;
        float2 bv = *(const float2*)(bias + c);
#pragma unroll
        for (int mt = 0; mt < 2; mt++) {
            int r = r_base + mt * 16;
            if (r < M) {
                __nv_bfloat162 v = __floats2bfloat162_rn(acc[mt][nt][0] + bv.x, acc[mt][nt][1] + bv.y);
                *(__nv_bfloat162*)(C + (size_t)r * 256 + c) = v;
            }
            if (r + 8 < M) {
                __nv_bfloat162 v = __floats2bfloat162_rn(acc[mt][nt][2] + bv.x, acc[mt][nt][3] + bv.y);
                *(__nv_bfloat162*)(C + (size_t)(r + 8) * 256 + c) = v;
            }
        }
    }
}

// ---------------- edge GEMM: eproj_bf16[i] = (easorted @ We)[i], CSR row order ----------------
__global__ __launch_bounds__(256)
void gemm_edge(const float* __restrict__ W) {
    __shared__ __align__(16) float As[128][36];
    __shared__ __align__(16) float Bs[32][136];
    const float* A = g_easorted;
    const int tid = threadIdx.x, warp = tid >> 5, lane = tid & 31;
    const int warp_m = warp & 3, warp_n = warp >> 2;
    const int row0 = blockIdx.x * 128;
    const int col0 = blockIdx.y * 128;
    const int lq = lane >> 2, lr = lane & 3;
    const int M = NEDGES;

    GEMM_BODY(A, W, 64, M, row0, col0)

    const int r_base = row0 + warp_m * 32 + lq;
    const int c_base = col0 + warp_n * 64 + lr * 2;
#pragma unroll
    for (int nt = 0; nt < 8; nt++) {
        int c = c_base + nt * 8;
#pragma unroll
        for (int mt = 0; mt < 2; mt++) {
            int r = r_base + mt * 16;
            if (r < M) {
                __nv_bfloat162 v = __floats2bfloat162_rn(acc[mt][nt][0], acc[mt][nt][1]);
                *(__nv_bfloat162*)(g_eproj + (size_t)r * 256 + c) = v;
            }
            if (r + 8 < M) {
                __nv_bfloat162 v = __floats2bfloat162_rn(acc[mt][nt][2], acc[mt][nt][3]);
                *(__nv_bfloat162*)(g_eproj + (size_t)(r + 8) * 256 + c) = v;
            }
        }
    }
}

// ---------------- CSR build (once per launch) ----------------
__global__ void hist_kernel(const int* __restrict__ dst) {
    int e = blockIdx.x * blockDim.x + threadIdx.x;
    if (e < NEDGES) atomicAdd(&g_cnt[dst[e]], 1);
}
__global__ void blocksum_kernel() {
    int i = blockIdx.x * 256 + threadIdx.x;
    int v = (i < NNODES) ? g_cnt[i] : 0;
    __shared__ int ws[8];
#pragma unroll
    for (int o = 16; o; o >>= 1) v += __shfl_down_sync(0xffffffffu, v, o);
    if ((threadIdx.x & 31) == 0) ws[threadIdx.x >> 5] = v;
    __syncthreads();
    if (threadIdx.x == 0) {
        int s = 0;
#pragma unroll
        for (int j = 0; j < 8; j++) s += ws[j];
        g_bsum[blockIdx.x] = s;
    }
}
__global__ void scanb_kernel() {
    __shared__ int sm[512];
    int i = threadIdx.x;
    int v = (i < NBLK) ? g_bsum[i] : 0;
    sm[i] = v;
    __syncthreads();
    for (int s = 1; s < 512; s <<= 1) {
        int t = (i >= s) ? sm[i - s] : 0;
        __syncthreads();
        sm[i] += t;
        __syncthreads();
    }
    if (i < NBLK) g_bsum[i] = sm[i] - v;
}
__global__ void rowptr_kernel() {
    int tid = threadIdx.x;
    int i = blockIdx.x * 256 + tid;
    int v = (i < NNODES) ? g_cnt[i] : 0;
    __shared__ int sm[256];
    sm[tid] = v;
    __syncthreads();
    for (int s = 1; s < 256; s <<= 1) {
        int t = (tid >= s) ? sm[tid - s] : 0;
        __syncthreads();
        sm[tid] += t;
        __syncthreads();
    }
    int ex = sm[tid] - v + g_bsum[blockIdx.x];
    if (i < NNODES) { g_rowptr[i] = ex; g_woff[i] = ex; }
    if (i == NNODES - 1) g_rowptr[NNODES] = NEDGES;
}
__global__ void fill_kernel(const int* __restrict__ src, const int* __restrict__ dst) {
    int e = blockIdx.x * blockDim.x + threadIdx.x;
    if (e >= NEDGES) return;
    int d = dst[e];
    int pos = atomicAdd(&g_woff[d], 1);
    g_ssrc[pos] = src[e];
    g_seid[pos] = e;
}
__global__ void permute_ea_kernel(const float* __restrict__ ea) {
    int gt = blockIdx.x * blockDim.x + threadIdx.x;
    if (gt >= NEDGES * 16) return;
    int i = gt >> 4, q = gt & 15;
    int e = g_seid[i];
    ((float4*)g_easorted)[(size_t)i * 16 + q] = ((const float4*)ea)[(size_t)e * 16 + q];
}

// ---------------- edge_attr column sums (once) ----------------
__global__ void esum_kernel(const float* __restrict__ ea) {
    int col = threadIdx.x & 63;
    int rowsPerBlk = blockDim.x >> 6;
    int r0 = blockIdx.x * rowsPerBlk + (threadIdx.x >> 6);
    int rstride = gridDim.x * rowsPerBlk;
    float s = 0.0f;
    for (int r = r0; r < NEDGES; r += rstride) s += ea[(size_t)r * EDIM + col];
    atomicAdd(&g_esum[col], s);
}
__global__ void eloop_kernel(const float* __restrict__ We) {
    int j = threadIdx.x;
    const float inv = 1.0f / (float)NEDGES;
    float acc = 0.0f;
#pragma unroll
    for (int k = 0; k < EDIM; k++) acc = fmaf(g_esum[k] * inv, We[k * 256 + j], acc);
    g_eloop[j] = acc;
}

// ---------------- fused GAT edge phase: warp per dst node ----------------
__global__ __launch_bounds__(256)
void fused_gat_kernel(const float* __restrict__ att, const float* __restrict__ bias,
                      float* __restrict__ xn) {
    int gt = blockIdx.x * blockDim.x + threadIdx.x;
    int d = gt >> 5, lane = gt & 31;
    if (d >= NNODES) return;
    const int off = lane * 8;

    float4 xr0, xr1;
    ld8bf16(g_xr + (size_t)d * 256 + off, xr0, xr1);
    float4 at0 = *(const float4*)(att + off);
    float4 at1 = *(const float4*)(att + off + 4);

    float acc[8];
    float denom;
    // ---- self loop: src = d, edge feature = eloop (fp32) ----
    {
        float4 a0, a1;
        ld8bf16(g_xl + (size_t)d * 256 + off, a0, a1);
        float4 e0 = *(const float4*)(g_eloop + off);
        float4 e1 = *(const float4*)(g_eloop + off + 4);
        float t = 0.0f, m;
        m = a0.x + xr0.x + e0.x; m = fmaxf(m, 0.2f * m); t = fmaf(m, at0.x, t);
        m = a0.y + xr0.y + e0.y; m = fmaxf(m, 0.2f * m); t = fmaf(m, at0.y, t);
        m = a0.z + xr0.z + e0.z; m = fmaxf(m, 0.2f * m); t = fmaf(m, at0.z, t);
        m = a0.w + xr0.w + e0.w; m = fmaxf(m, 0.2f * m); t = fmaf(m, at0.w, t);
        m = a1.x + xr1.x + e1.x; m = fmaxf(m, 0.2f * m); t = fmaf(m, at1.x, t);
        m = a1.y + xr1.y + e1.y; m = fmaxf(m, 0.2f * m); t = fmaf(m, at1.y, t);
        m = a1.z + xr1.z + e1.z; m = fmaxf(m, 0.2f * m); t = fmaf(m, at1.z, t);
        m = a1.w + xr1.w + e1.w; m = fmaxf(m, 0.2f * m); t = fmaf(m, at1.w, t);
        t += __shfl_down_sync(0xffffffffu, t, 4, 8);
        t += __shfl_down_sync(0xffffffffu, t, 2, 8);
        t += __shfl_down_sync(0xffffffffu, t, 1, 8);
        float p = __expf(__shfl_sync(0xffffffffu, t, 0, 8));
        denom = p;
        acc[0] = p * a0.x; acc[1] = p * a0.y; acc[2] = p * a0.z; acc[3] = p * a0.w;
        acc[4] = p * a1.x; acc[5] = p * a1.y; acc[6] = p * a1.z; acc[7] = p * a1.w;
    }
    // ---- real edges: CSR order, eproj sequential bf16, xl gathers bf16 ----
    const int beg = g_rowptr[d], end = g_rowptr[d + 1];
    for (int i = beg; i < end; i++) {
        int s = g_ssrc[i];
        float4 a0, a1, e0, e1;
        ld8bf16(g_xl + (size_t)s * 256 + off, a0, a1);
        ld8bf16(g_eproj + (size_t)i * 256 + off, e0, e1);
        float t = 0.0f, m;
        m = a0.x + xr0.x + e0.x; m = fmaxf(m, 0.2f * m); t = fmaf(m, at0.x, t);
        m = a0.y + xr0.y + e0.y; m = fmaxf(m, 0.2f * m); t = fmaf(m, at0.y, t);
        m = a0.z + xr0.z + e0.z; m = fmaxf(m, 0.2f * m); t = fmaf(m, at0.z, t);
        m = a0.w + xr0.w + e0.w; m = fmaxf(m, 0.2f * m); t = fmaf(m, at0.w, t);
        m = a1.x + xr1.x + e1.x; m = fmaxf(m, 0.2f * m); t = fmaf(m, at1.x, t);
        m = a1.y + xr1.y + e1.y; m = fmaxf(m, 0.2f * m); t = fmaf(m, at1.y, t);
        m = a1.z + xr1.z + e1.z; m = fmaxf(m, 0.2f * m); t = fmaf(m, at1.z, t);
        m = a1.w + xr1.w + e1.w; m = fmaxf(m, 0.2f * m); t = fmaf(m, at1.w, t);
        t += __shfl_down_sync(0xffffffffu, t, 4, 8);
        t += __shfl_down_sync(0xffffffffu, t, 2, 8);
        t += __shfl_down_sync(0xffffffffu, t, 1, 8);
        float p = __expf(__shfl_sync(0xffffffffu, t, 0, 8));
        denom += p;
        acc[0] = fmaf(p, a0.x, acc[0]); acc[1] = fmaf(p, a0.y, acc[1]);
        acc[2] = fmaf(p, a0.z, acc[2]); acc[3] = fmaf(p, a0.w, acc[3]);
        acc[4] = fmaf(p, a1.x, acc[4]); acc[5] = fmaf(p, a1.y, acc[5]);
        acc[6] = fmaf(p, a1.z, acc[6]); acc[7] = fmaf(p, a1.w, acc[7]);
    }
    float inv = 1.0f / (denom + 1e-16f);
    float4 b0 = *(const float4*)(bias + off);
    float4 b1 = *(const float4*)(bias + off + 4);
    float4 o0, o1;
    o0.x = fmaxf(fmaf(acc[0], inv, b0.x), 0.f); o0.y = fmaxf(fmaf(acc[1], inv, b0.y), 0.f);
    o0.z = fmaxf(fmaf(acc[2], inv, b0.z), 0.f); o0.w = fmaxf(fmaf(acc[3], inv, b0.w), 0.f);
    o1.x = fmaxf(fmaf(acc[4], inv, b1.x), 0.f); o1.y = fmaxf(fmaf(acc[5], inv, b1.y), 0.f);
    o1.z = fmaxf(fmaf(acc[6], inv, b1.z), 0.f); o1.w = fmaxf(fmaf(acc[7], inv, b1.w), 0.f);
    *(float4*)(xn + (size_t)d * 256 + off) = o0;
    *(float4*)(xn + (size_t)d * 256 + off + 4) = o1;
}

// ---------------- global mean pool ----------------
__global__ void pool_kernel(const int* __restrict__ batch, const float* __restrict__ xf) {
    int gt = blockIdx.x * blockDim.x + threadIdx.x;
    int node = gt >> 5, lane = gt & 31;
    if (node >= NNODES) return;
    int g = batch[node];
    const float4* xs = (const float4*)(xf + (size_t)node * 256) + lane * 2;
    float4 v0 = xs[0], v1 = xs[1];
    float* bp = g_gsum + (size_t)g * 256 + lane * 8;
    red4(bp,     v0.x, v0.y, v0.z, v0.w);
    red4(bp + 4, v1.x, v1.y, v1.z, v1.w);
    if (lane == 0) atomicAdd(&g_gcnt[g], 1.0f);
}

// ---------------- final MLP ----------------
__global__ __launch_bounds__(128)
void mlp_kernel(const float* __restrict__ Wp1, const float* __restrict__ bp1,
                const float* __restrict__ Wp2, const float* __restrict__ bp2,
                float* __restrict__ out) {
    int g = blockIdx.x;
    __shared__ float pooled[256];
    __shared__ float partial[4];
    float cnt = fmaxf(g_gcnt[g], 1.0f);
    for (int i = threadIdx.x; i < 256; i += 128)
        pooled[i] = g_gsum[(size_t)g * 256 + i] / cnt;
    __syncthreads();
    int j = threadIdx.x;
    float acc = bp1[j];
#pragma unroll 8
    for (int k = 0; k < 256; k++) acc = fmaf(pooled[k], Wp1[k * 128 + j], acc);
    float h = fmaxf(acc, 0.0f) * Wp2[j];
#pragma unroll
    for (int o = 16; o; o >>= 1) h += __shfl_down_sync(0xffffffffu, h, o);
    if ((threadIdx.x & 31) == 0) partial[threadIdx.x >> 5] = h;
    __syncthreads();
    if (threadIdx.x == 0)
        out[g] = partial[0] + partial[1] + partial[2] + partial[3] + bp2[0];
}

// ---------------- launcher ----------------
extern "C" void kernel_launch(void* const* d_in, const int* in_sizes, int n_in,
                              void* d_out, int out_size) {
    const float* x     = (const float*)d_in[0];
    const int*   ei    = (const int*)  d_in[1];
    const float* ea    = (const float*)d_in[2];
    const int*   batch = (const int*)  d_in[3];
    const float* Wl    = (const float*)d_in[4];
    const float* bl    = (const float*)d_in[5];
    const float* Wr    = (const float*)d_in[6];
    const float* br    = (const float*)d_in[7];
    const float* We    = (const float*)d_in[8];
    const float* att   = (const float*)d_in[9];
    const float* bias  = (const float*)d_in[10];
    const float* Wp1   = (const float*)d_in[11];
    const float* bp1   = (const float*)d_in[12];
    const float* Wp2   = (const float*)d_in[13];
    const float* bp2   = (const float*)d_in[14];
    float* out = (float*)d_out;
    const int* src = ei;
    const int* dst = ei + NEDGES;

    float *bufA, *bufB, *esum, *gsum, *gcnt;
    __nv_bfloat16 *xl, *xr;
    int* cnt;
    cudaGetSymbolAddress((void**)&bufA,  g_bufA);
    cudaGetSymbolAddress((void**)&bufB,  g_bufB);
    cudaGetSymbolAddress((void**)&xl,    g_xl);
    cudaGetSymbolAddress((void**)&xr,    g_xr);
    cudaGetSymbolAddress((void**)&esum,  g_esum);
    cudaGetSymbolAddress((void**)&gsum,  g_gsum);
    cudaGetSymbolAddress((void**)&gcnt,  g_gcnt);
    cudaGetSymbolAddress((void**)&cnt,   g_cnt);

    // ---- CSR build + ea permutation (topology constant) ----
    cudaMemsetAsync(cnt, 0, NNODES * sizeof(int));
    hist_kernel<<<(NEDGES + 255) / 256, 256>>>(dst);
    blocksum_kernel<<<NBLK, 256>>>();
    scanb_kernel<<<1, 512>>>();
    rowptr_kernel<<<NBLK, 256>>>();
    fill_kernel<<<(NEDGES + 255) / 256, 256>>>(src, dst);
    permute_ea_kernel<<<(NEDGES * 16 + 255) / 256, 256>>>(ea);

    cudaMemsetAsync(esum, 0, EDIM * sizeof(float));
    esum_kernel<<<512, 256>>>(ea);

    const float* xcur = x;
    for (int l = 0; l < NLAYER; l++) {
        float* xn = (l & 1) ? bufB : bufA;
        dim3 gN((NNODES + 127) / 128, 4);
        gemm_node<<<gN, 256>>>(xcur, Wl + (size_t)l * 256 * 256, Wr + (size_t)l * 256 * 256,
                               bl + l * 256, br + l * 256, xl, xr, NNODES);
        dim3 gE((NEDGES + 127) / 128, 2);
        gemm_edge<<<gE, 256>>>(We + (size_t)l * 64 * 256);
        eloop_kernel<<<1, 256>>>(We + (size_t)l * 64 * 256);

        fused_gat_kernel<<<(NNODES * 32 + 255) / 256, 256>>>(att + l * 256, bias + l * 256, xn);
        xcur = xn;
    }

    cudaMemsetAsync(gsum, 0, (size_t)GDIM * 256 * sizeof(float));
    cudaMemsetAsync(gcnt, 0, GDIM * sizeof(float));
    pool_kernel<<<(NNODES * 32 + 255) / 256, 256>>>(batch, xcur);
    mlp_kernel<<<GDIM, 128>>>(Wp1, bp1, Wp2, bp2, out);
}

// round 9
// speedup vs baseline: 1.3384x; 1.1176x over previous
#include <cuda_runtime.h>
#include <cuda_bf16.h>
#include <cstdint>

#define NNODES 100000
#define NEDGES 300000
#define GDIM   2048
#define HIDDIM 256
#define EDIM   64
#define NLAYER 3
#define NBLK   ((NNODES + 255) / 256)   // 391

// ---------------- static device scratch ----------------
__device__ float g_bufA[(size_t)NNODES * HIDDIM];
__device__ float g_bufB[(size_t)NNODES * HIDDIM];
__device__ __nv_bfloat16 g_xl[(size_t)NNODES * HIDDIM];
__device__ __nv_bfloat16 g_xr[(size_t)NNODES * HIDDIM];
__device__ __nv_bfloat16 g_eproj[(size_t)NEDGES * HIDDIM]; // bf16, CSR-sorted order
__device__ float g_easorted[(size_t)NEDGES * EDIM];        // edge_attr in CSR order
__device__ float g_eloop[HIDDIM];
__device__ float g_esum[EDIM];
__device__ float g_gsum[(size_t)GDIM * HIDDIM];
__device__ float g_gcnt[GDIM];
// CSR (dst-sorted edges)
__device__ int g_cnt[NNODES];
__device__ int g_bsum[512];
__device__ int g_rowptr[NNODES + 1];
__device__ int g_woff[NNODES];
__device__ int g_ssrc[NEDGES];
__device__ int g_seid[NEDGES];

// ---------------- helpers ----------------
__device__ __forceinline__ void red4(float* p, float a, float b, float c, float d) {
    asm volatile("red.global.add.v4.f32 [%0], {%1,%2,%3,%4};"
                 :: "l"(p), "f"(a), "f"(b), "f"(c), "f"(d) : "memory");
}
__device__ __forceinline__ void mma_tf32(float* c, const uint32_t* a, const uint32_t* b) {
    asm volatile("mma.sync.aligned.m16n8k8.row.col.f32.tf32.tf32.f32 "
                 "{%0,%1,%2,%3}, {%4,%5,%6,%7}, {%8,%9}, {%0,%1,%2,%3};"
                 : "+f"(c[0]), "+f"(c[1]), "+f"(c[2]), "+f"(c[3])
                 : "r"(a[0]), "r"(a[1]), "r"(a[2]), "r"(a[3]), "r"(b[0]), "r"(b[1]));
}
__device__ __forceinline__ void cp16(void* smem, const void* gmem) {
    uint32_t s;
    asm("{ .reg .u64 t; cvta.to.shared.u64 t, %1; cvt.u32.u64 %0, t; }" : "=r"(s) : "l"(smem));
    asm volatile("cp.async.cg.shared.global [%0], [%1], 16;" :: "r"(s), "l"(gmem));
}
// expand 8 packed bf16 (uint4) to two float4
__device__ __forceinline__ void bf16x8_expand(uint4 u, float4& o0, float4& o1) {
    float2 f0 = __bfloat1622float2(*(__nv_bfloat162*)&u.x);
    float2 f1 = __bfloat1622float2(*(__nv_bfloat162*)&u.y);
    float2 f2 = __bfloat1622float2(*(__nv_bfloat162*)&u.z);
    float2 f3 = __bfloat1622float2(*(__nv_bfloat162*)&u.w);
    o0 = make_float4(f0.x, f0.y, f1.x, f1.y);
    o1 = make_float4(f2.x, f2.y, f3.x, f3.y);
}
__device__ __forceinline__ void ld8bf16(const __nv_bfloat16* p, float4& o0, float4& o1) {
    bf16x8_expand(*(const uint4*)p, o0, o1);
}

// ========== GEMM: cp.async 2-stage pipeline, BK=16, CTA 128x128, 8 warps 4x2 ==========
#define GEMM_LOAD(s, k0, A, W, K, M, row0, col0)                                      \
    _Pragma("unroll") for (int i = 0; i < 2; i++) {                                   \
        int idx = tid + i * 256;                                                      \
        int r = idx >> 2, q = idx & 3;                                                \
        int ar = (row0) + r; if (ar >= (M)) ar = (M) - 1;                             \
        cp16(&As[s][r][q * 4], A + (size_t)ar * (K) + (k0) + q * 4);                  \
        int rb = idx >> 5, qb = idx & 31;                                             \
        cp16(&Bs[s][rb][qb * 4], W + (size_t)((k0) + rb) * 256 + (col0) + qb * 4);    \
    }                                                                                 \
    asm volatile("cp.async.commit_group;" ::: "memory");

#define GEMM_BODY(A, W, K, M, row0, col0)                                             \
    float acc[2][8][4];                                                               \
    _Pragma("unroll") for (int mt = 0; mt < 2; mt++)                                  \
    _Pragma("unroll") for (int nt = 0; nt < 8; nt++)                                  \
    _Pragma("unroll") for (int i = 0; i < 4; i++) acc[mt][nt][i] = 0.0f;              \
    GEMM_LOAD(0, 0, A, W, K, M, row0, col0)                                           \
    const int NKC = (K) / 16;                                                         \
    for (int kc = 0; kc < NKC; kc++) {                                                \
        if (kc + 1 < NKC) {                                                           \
            GEMM_LOAD((kc + 1) & 1, (kc + 1) * 16, A, W, K, M, row0, col0)            \
            asm volatile("cp.async.wait_group 1;" ::: "memory");                      \
        } else {                                                                      \
            asm volatile("cp.async.wait_group 0;" ::: "memory");                      \
        }                                                                             \
        __syncthreads();                                                              \
        const int st = kc & 1;                                                        \
        _Pragma("unroll") for (int ks = 0; ks < 2; ks++) {                            \
            const int kb = ks * 8;                                                    \
            uint32_t bf[8][2];                                                        \
            const int brow = kb + lr, bcol = warp_n * 64 + lq;                        \
            _Pragma("unroll") for (int nt = 0; nt < 8; nt++) {                        \
                bf[nt][0] = __float_as_uint(Bs[st][brow][bcol + nt * 8]);             \
                bf[nt][1] = __float_as_uint(Bs[st][brow + 4][bcol + nt * 8]);         \
            }                                                                         \
            _Pragma("unroll") for (int mt = 0; mt < 2; mt++) {                        \
                uint32_t af[4];                                                       \
                const int arow = warp_m * 32 + mt * 16 + lq;                          \
                af[0] = __float_as_uint(As[st][arow][kb + lr]);                       \
                af[1] = __float_as_uint(As[st][arow + 8][kb + lr]);                   \
                af[2] = __float_as_uint(As[st][arow][kb + 4 + lr]);                   \
                af[3] = __float_as_uint(As[st][arow + 8][kb + 4 + lr]);               \
                _Pragma("unroll") for (int nt = 0; nt < 8; nt++)                      \
                    mma_tf32(acc[mt][nt], af, bf[nt]);                                \
            }                                                                         \
        }                                                                             \
        __syncthreads();                                                              \
    }

// ---------------- fused node GEMM: xl = A@Wl+bl, xr = A@Wr+br (bf16 out) ----------------
__global__ __launch_bounds__(256)
void gemm_node(const float* __restrict__ A,
               const float* __restrict__ Wl_, const float* __restrict__ Wr_,
               const float* __restrict__ bl_, const float* __restrict__ br_,
               __nv_bfloat16* __restrict__ Cl, __nv_bfloat16* __restrict__ Cr, int M) {
    __shared__ __align__(16) float As[2][128][20];
    __shared__ __align__(16) float Bs[2][16][136];
    const int tid = threadIdx.x, warp = tid >> 5, lane = tid & 31;
    const int warp_m = warp & 3, warp_n = warp >> 2;
    const int row0 = blockIdx.x * 128;
    const int col0 = (blockIdx.y & 1) * 128;
    const float* W    = (blockIdx.y < 2) ? Wl_ : Wr_;
    const float* bias = (blockIdx.y < 2) ? bl_ : br_;
    __nv_bfloat16* C  = (blockIdx.y < 2) ? Cl  : Cr;
    const int lq = lane >> 2, lr = lane & 3;

    GEMM_BODY(A, W, 256, M, row0, col0)

    const int r_base = row0 + warp_m * 32 + lq;
    const int c_base = col0 + warp_n * 64 + lr * 2;
#pragma unroll
    for (int nt = 0; nt < 8; nt++) {
        int c = c_base + nt * 8;
        float2 bv = *(const float2*)(bias + c);
#pragma unroll
        for (int mt = 0; mt < 2; mt++) {
            int r = r_base + mt * 16;
            if (r < M) {
                __nv_bfloat162 v = __floats2bfloat162_rn(acc[mt][nt][0] + bv.x, acc[mt][nt][1] + bv.y);
                *(__nv_bfloat162*)(C + (size_t)r * 256 + c) = v;
            }
            if (r + 8 < M) {
                __nv_bfloat162 v = __floats2bfloat162_rn(acc[mt][nt][2] + bv.x, acc[mt][nt][3] + bv.y);
                *(__nv_bfloat162*)(C + (size_t)(r + 8) * 256 + c) = v;
            }
        }
    }
}

// ---------------- edge GEMM: eproj_bf16[i] = (easorted @ We)[i], CSR row order ----------------
__global__ __launch_bounds__(256)
void gemm_edge(const float* __restrict__ W) {
    __shared__ __align__(16) float As[2][128][20];
    __shared__ __align__(16) float Bs[2][16][136];
    const float* A = g_easorted;
    const int tid = threadIdx.x, warp = tid >> 5, lane = tid & 31;
    const int warp_m = warp & 3, warp_n = warp >> 2;
    const int row0 = blockIdx.x * 128;
    const int col0 = blockIdx.y * 128;
    const int lq = lane >> 2, lr = lane & 3;
    const int M = NEDGES;

    GEMM_BODY(A, W, 64, M, row0, col0)

    const int r_base = row0 + warp_m * 32 + lq;
    const int c_base = col0 + warp_n * 64 + lr * 2;
#pragma unroll
    for (int nt = 0; nt < 8; nt++) {
        int c = c_base + nt * 8;
#pragma unroll
        for (int mt = 0; mt < 2; mt++) {
            int r = r_base + mt * 16;
            if (r < M) {
                __nv_bfloat162 v = __floats2bfloat162_rn(acc[mt][nt][0], acc[mt][nt][1]);
                *(__nv_bfloat162*)(g_eproj + (size_t)r * 256 + c) = v;
            }
            if (r + 8 < M) {
                __nv_bfloat162 v = __floats2bfloat162_rn(acc[mt][nt][2], acc[mt][nt][3]);
                *(__nv_bfloat162*)(g_eproj + (size_t)(r + 8) * 256 + c) = v;
            }
        }
    }
}

// ---------------- CSR build (once per launch) ----------------
__global__ void hist_kernel(const int* __restrict__ dst) {
    int e = blockIdx.x * blockDim.x + threadIdx.x;
    if (e < NEDGES) atomicAdd(&g_cnt[dst[e]], 1);
}
__global__ void blocksum_kernel() {
    int i = blockIdx.x * 256 + threadIdx.x;
    int v = (i < NNODES) ? g_cnt[i] : 0;
    __shared__ int ws[8];
#pragma unroll
    for (int o = 16; o; o >>= 1) v += __shfl_down_sync(0xffffffffu, v, o);
    if ((threadIdx.x & 31) == 0) ws[threadIdx.x >> 5] = v;
    __syncthreads();
    if (threadIdx.x == 0) {
        int s = 0;
#pragma unroll
        for (int j = 0; j < 8; j++) s += ws[j];
        g_bsum[blockIdx.x] = s;
    }
}
__global__ void scanb_kernel() {
    __shared__ int sm[512];
    int i = threadIdx.x;
    int v = (i < NBLK) ? g_bsum[i] : 0;
    sm[i] = v;
    __syncthreads();
    for (int s = 1; s < 512; s <<= 1) {
        int t = (i >= s) ? sm[i - s] : 0;
        __syncthreads();
        sm[i] += t;
        __syncthreads();
    }
    if (i < NBLK) g_bsum[i] = sm[i] - v;
}
__global__ void rowptr_kernel() {
    int tid = threadIdx.x;
    int i = blockIdx.x * 256 + tid;
    int v = (i < NNODES) ? g_cnt[i] : 0;
    __shared__ int sm[256];
    sm[tid] = v;
    __syncthreads();
    for (int s = 1; s < 256; s <<= 1) {
        int t = (tid >= s) ? sm[tid - s] : 0;
        __syncthreads();
        sm[tid] += t;
        __syncthreads();
    }
    int ex = sm[tid] - v + g_bsum[blockIdx.x];
    if (i < NNODES) { g_rowptr[i] = ex; g_woff[i] = ex; }
    if (i == NNODES - 1) g_rowptr[NNODES] = NEDGES;
}
__global__ void fill_kernel(const int* __restrict__ src, const int* __restrict__ dst) {
    int e = blockIdx.x * blockDim.x + threadIdx.x;
    if (e >= NEDGES) return;
    int d = dst[e];
    int pos = atomicAdd(&g_woff[d], 1);
    g_ssrc[pos] = src[e];
    g_seid[pos] = e;
}
__global__ void permute_ea_kernel(const float* __restrict__ ea) {
    int gt = blockIdx.x * blockDim.x + threadIdx.x;
    if (gt >= NEDGES * 16) return;
    int i = gt >> 4, q = gt & 15;
    int e = g_seid[i];
    ((float4*)g_easorted)[(size_t)i * 16 + q] = ((const float4*)ea)[(size_t)e * 16 + q];
}

// ---------------- edge_attr column sums (once) ----------------
__global__ void esum_kernel(const float* __restrict__ ea) {
    int col = threadIdx.x & 63;
    int rowsPerBlk = blockDim.x >> 6;
    int r0 = blockIdx.x * rowsPerBlk + (threadIdx.x >> 6);
    int rstride = gridDim.x * rowsPerBlk;
    float s = 0.0f;
    for (int r = r0; r < NEDGES; r += rstride) s += ea[(size_t)r * EDIM + col];
    atomicAdd(&g_esum[col], s);
}
__global__ void eloop_kernel(const float* __restrict__ We) {
    int j = threadIdx.x;
    const float inv = 1.0f / (float)NEDGES;
    float acc = 0.0f;
#pragma unroll
    for (int k = 0; k < EDIM; k++) acc = fmaf(g_esum[k] * inv, We[k * 256 + j], acc);
    g_eloop[j] = acc;
}

// ---------------- fused GAT edge phase: warp per dst node, 2-deep edge pipeline ----------------
__global__ __launch_bounds__(256)
void fused_gat_kernel(const float* __restrict__ att, const float* __restrict__ bias,
                      float* __restrict__ xn) {
    int gt = blockIdx.x * blockDim.x + threadIdx.x;
    int d = gt >> 5, lane = gt & 31;
    if (d >= NNODES) return;
    const int off = lane * 8;

    float4 xr0, xr1;
    ld8bf16(g_xr + (size_t)d * 256 + off, xr0, xr1);
    float4 at0 = *(const float4*)(att + off);
    float4 at1 = *(const float4*)(att + off + 4);

    float acc[8];
    float denom;
    // ---- self loop: src = d, edge feature = eloop (fp32) ----
    {
        float4 a0, a1;
        ld8bf16(g_xl + (size_t)d * 256 + off, a0, a1);
        float4 e0 = *(const float4*)(g_eloop + off);
        float4 e1 = *(const float4*)(g_eloop + off + 4);
        float t = 0.0f, m;
        m = a0.x + xr0.x + e0.x; m = fmaxf(m, 0.2f * m); t = fmaf(m, at0.x, t);
        m = a0.y + xr0.y + e0.y; m = fmaxf(m, 0.2f * m); t = fmaf(m, at0.y, t);
        m = a0.z + xr0.z + e0.z; m = fmaxf(m, 0.2f * m); t = fmaf(m, at0.z, t);
        m = a0.w + xr0.w + e0.w; m = fmaxf(m, 0.2f * m); t = fmaf(m, at0.w, t);
        m = a1.x + xr1.x + e1.x; m = fmaxf(m, 0.2f * m); t = fmaf(m, at1.x, t);
        m = a1.y + xr1.y + e1.y; m = fmaxf(m, 0.2f * m); t = fmaf(m, at1.y, t);
        m = a1.z + xr1.z + e1.z; m = fmaxf(m, 0.2f * m); t = fmaf(m, at1.z, t);
        m = a1.w + xr1.w + e1.w; m = fmaxf(m, 0.2f * m); t = fmaf(m, at1.w, t);
        t += __shfl_down_sync(0xffffffffu, t, 4, 8);
        t += __shfl_down_sync(0xffffffffu, t, 2, 8);
        t += __shfl_down_sync(0xffffffffu, t, 1, 8);
        float p = __expf(__shfl_sync(0xffffffffu, t, 0, 8));
        denom = p;
        acc[0] = p * a0.x; acc[1] = p * a0.y; acc[2] = p * a0.z; acc[3] = p * a0.w;
        acc[4] = p * a1.x; acc[5] = p * a1.y; acc[6] = p * a1.z; acc[7] = p * a1.w;
    }
    // ---- real edges: CSR order, prefetch next edge's rows while computing current ----
    const int beg = g_rowptr[d], end = g_rowptr[d + 1];
    uint4 au, eu;
    if (beg < end) {
        int s = g_ssrc[beg];
        au = *(const uint4*)(g_xl + (size_t)s * 256 + off);
        eu = *(const uint4*)(g_eproj + (size_t)beg * 256 + off);
    }
    for (int i = beg; i < end; i++) {
        uint4 a_cur = au, e_cur = eu;
        if (i + 1 < end) {
            int s = g_ssrc[i + 1];
            au = *(const uint4*)(g_xl + (size_t)s * 256 + off);
            eu = *(const uint4*)(g_eproj + (size_t)(i + 1) * 256 + off);
        }
        float4 a0, a1, e0, e1;
        bf16x8_expand(a_cur, a0, a1);
        bf16x8_expand(e_cur, e0, e1);
        float t = 0.0f, m;
        m = a0.x + xr0.x + e0.x; m = fmaxf(m, 0.2f * m); t = fmaf(m, at0.x, t);
        m = a0.y + xr0.y + e0.y; m = fmaxf(m, 0.2f * m); t = fmaf(m, at0.y, t);
        m = a0.z + xr0.z + e0.z; m = fmaxf(m, 0.2f * m); t = fmaf(m, at0.z, t);
        m = a0.w + xr0.w + e0.w; m = fmaxf(m, 0.2f * m); t = fmaf(m, at0.w, t);
        m = a1.x + xr1.x + e1.x; m = fmaxf(m, 0.2f * m); t = fmaf(m, at1.x, t);
        m = a1.y + xr1.y + e1.y; m = fmaxf(m, 0.2f * m); t = fmaf(m, at1.y, t);
        m = a1.z + xr1.z + e1.z; m = fmaxf(m, 0.2f * m); t = fmaf(m, at1.z, t);
        m = a1.w + xr1.w + e1.w; m = fmaxf(m, 0.2f * m); t = fmaf(m, at1.w, t);
        t += __shfl_down_sync(0xffffffffu, t, 4, 8);
        t += __shfl_down_sync(0xffffffffu, t, 2, 8);
        t += __shfl_down_sync(0xffffffffu, t, 1, 8);
        float p = __expf(__shfl_sync(0xffffffffu, t, 0, 8));
        denom += p;
        acc[0] = fmaf(p, a0.x, acc[0]); acc[1] = fmaf(p, a0.y, acc[1]);
        acc[2] = fmaf(p, a0.z, acc[2]); acc[3] = fmaf(p, a0.w, acc[3]);
        acc[4] = fmaf(p, a1.x, acc[4]); acc[5] = fmaf(p, a1.y, acc[5]);
        acc[6] = fmaf(p, a1.z, acc[6]); acc[7] = fmaf(p, a1.w, acc[7]);
    }
    float inv = 1.0f / (denom + 1e-16f);
    float4 b0 = *(const float4*)(bias + off);
    float4 b1 = *(const float4*)(bias + off + 4);
    float4 o0, o1;
    o0.x = fmaxf(fmaf(acc[0], inv, b0.x), 0.f); o0.y = fmaxf(fmaf(acc[1], inv, b0.y), 0.f);
    o0.z = fmaxf(fmaf(acc[2], inv, b0.z), 0.f); o0.w = fmaxf(fmaf(acc[3], inv, b0.w), 0.f);
    o1.x = fmaxf(fmaf(acc[4], inv, b1.x), 0.f); o1.y = fmaxf(fmaf(acc[5], inv, b1.y), 0.f);
    o1.z = fmaxf(fmaf(acc[6], inv, b1.z), 0.f); o1.w = fmaxf(fmaf(acc[7], inv, b1.w), 0.f);
    *(float4*)(xn + (size_t)d * 256 + off) = o0;
    *(float4*)(xn + (size_t)d * 256 + off + 4) = o1;
}

// ---------------- global mean pool ----------------
__global__ void pool_kernel(const int* __restrict__ batch, const float* __restrict__ xf) {
    int gt = blockIdx.x * blockDim.x + threadIdx.x;
    int node = gt >> 5, lane = gt & 31;
    if (node >= NNODES) return;
    int g = batch[node];
    const float4* xs = (const float4*)(xf + (size_t)node * 256) + lane * 2;
    float4 v0 = xs[0], v1 = xs[1];
    float* bp = g_gsum + (size_t)g * 256 + lane * 8;
    red4(bp,     v0.x, v0.y, v0.z, v0.w);
    red4(bp + 4, v1.x, v1.y, v1.z, v1.w);
    if (lane == 0) atomicAdd(&g_gcnt[g], 1.0f);
}

// ---------------- final MLP ----------------
__global__ __launch_bounds__(128)
void mlp_kernel(const float* __restrict__ Wp1, const float* __restrict__ bp1,
                const float* __restrict__ Wp2, const float* __restrict__ bp2,
                float* __restrict__ out) {
    int g = blockIdx.x;
    __shared__ float pooled[256];
    __shared__ float partial[4];
    float cnt = fmaxf(g_gcnt[g], 1.0f);
    for (int i = threadIdx.x; i < 256; i += 128)
        pooled[i] = g_gsum[(size_t)g * 256 + i] / cnt;
    __syncthreads();
    int j = threadIdx.x;
    float acc = bp1[j];
#pragma unroll 8
    for (int k = 0; k < 256; k++) acc = fmaf(pooled[k], Wp1[k * 128 + j], acc);
    float h = fmaxf(acc, 0.0f) * Wp2[j];
#pragma unroll
    for (int o = 16; o; o >>= 1) h += __shfl_down_sync(0xffffffffu, h, o);
    if ((threadIdx.x & 31) == 0) partial[threadIdx.x >> 5] = h;
    __syncthreads();
    if (threadIdx.x == 0)
        out[g] = partial[0] + partial[1] + partial[2] + partial[3] + bp2[0];
}

// ---------------- launcher ----------------
extern "C" void kernel_launch(void* const* d_in, const int* in_sizes, int n_in,
                              void* d_out, int out_size) {
    const float* x     = (const float*)d_in[0];
    const int*   ei    = (const int*)  d_in[1];
    const float* ea    = (const float*)d_in[2];
    const int*   batch = (const int*)  d_in[3];
    const float* Wl    = (const float*)d_in[4];
    const float* bl    = (const float*)d_in[5];
    const float* Wr    = (const float*)d_in[6];
    const float* br    = (const float*)d_in[7];
    const float* We    = (const float*)d_in[8];
    const float* att   = (const float*)d_in[9];
    const float* bias  = (const float*)d_in[10];
    const float* Wp1   = (const float*)d_in[11];
    const float* bp1   = (const float*)d_in[12];
    const float* Wp2   = (const float*)d_in[13];
    const float* bp2   = (const float*)d_in[14];
    float* out = (float*)d_out;
    const int* src = ei;
    const int* dst = ei + NEDGES;

    float *bufA, *bufB, *esum, *gsum, *gcnt;
    __nv_bfloat16 *xl, *xr;
    int* cnt;
    cudaGetSymbolAddress((void**)&bufA,  g_bufA);
    cudaGetSymbolAddress((void**)&bufB,  g_bufB);
    cudaGetSymbolAddress((void**)&xl,    g_xl);
    cudaGetSymbolAddress((void**)&xr,    g_xr);
    cudaGetSymbolAddress((void**)&esum,  g_esum);
    cudaGetSymbolAddress((void**)&gsum,  g_gsum);
    cudaGetSymbolAddress((void**)&gcnt,  g_gcnt);
    cudaGetSymbolAddress((void**)&cnt,   g_cnt);

    // ---- CSR build + ea permutation (topology constant) ----
    cudaMemsetAsync(cnt, 0, NNODES * sizeof(int));
    hist_kernel<<<(NEDGES + 255) / 256, 256>>>(dst);
    blocksum_kernel<<<NBLK, 256>>>();
    scanb_kernel<<<1, 512>>>();
    rowptr_kernel<<<NBLK, 256>>>();
    fill_kernel<<<(NEDGES + 255) / 256, 256>>>(src, dst);
    permute_ea_kernel<<<(NEDGES * 16 + 255) / 256, 256>>>(ea);

    cudaMemsetAsync(esum, 0, EDIM * sizeof(float));
    esum_kernel<<<512, 256>>>(ea);

    const float* xcur = x;
    for (int l = 0; l < NLAYER; l++) {
        float* xn = (l & 1) ? bufB : bufA;
        dim3 gN((NNODES + 127) / 128, 4);
        gemm_node<<<gN, 256>>>(xcur, Wl + (size_t)l * 256 * 256, Wr + (size_t)l * 256 * 256,
                               bl + l * 256, br + l * 256, xl, xr, NNODES);
        dim3 gE((NEDGES + 127) / 128, 2);
        gemm_edge<<<gE, 256>>>(We + (size_t)l * 64 * 256);
        eloop_kernel<<<1, 256>>>(We + (size_t)l * 64 * 256);

        fused_gat_kernel<<<(NNODES * 32 + 255) / 256, 256>>>(att + l * 256, bias + l * 256, xn);
        xcur = xn;
    }

    cudaMemsetAsync(gsum, 0, (size_t)GDIM * 256 * sizeof(float));
    cudaMemsetAsync(gcnt, 0, GDIM * sizeof(float));
    pool_kernel<<<(NNODES * 32 + 255) / 256, 256>>>(batch, xcur);
    mlp_kernel<<<GDIM, 128>>>(Wp1, bp1, Wp2, bp2, out);
}

// round 10
// speedup vs baseline: 1.6365x; 1.2227x over previous
#include <cuda_runtime.h>
#include <cuda_fp16.h>
#include <cuda_bf16.h>
#include <cstdint>

#define NNODES 100000
#define NEDGES 300000
#define GDIM   2048
#define HIDDIM 256
#define EDIM   64
#define NLAYER 3
#define NBLK   ((NNODES + 255) / 256)   // 391

// ---------------- static device scratch ----------------
__device__ __half g_x16[(size_t)NNODES * HIDDIM];       // converted input
__device__ __half g_buf16A[(size_t)NNODES * HIDDIM];    // layer outputs (fp16)
__device__ __half g_buf16B[(size_t)NNODES * HIDDIM];
__device__ __half g_xl[(size_t)NNODES * HIDDIM];
__device__ __half g_xr[(size_t)NNODES * HIDDIM];
__device__ __half g_eproj[(size_t)NEDGES * HIDDIM];     // CSR-sorted order
__device__ __half g_ea16[(size_t)NEDGES * EDIM];        // edge_attr fp16, CSR order
__device__ __half g_wlt[(size_t)NLAYER * HIDDIM * HIDDIM];  // Wl^T [l][n][k] fp16
__device__ __half g_wrt[(size_t)NLAYER * HIDDIM * HIDDIM];  // Wr^T
__device__ __half g_wet[(size_t)NLAYER * HIDDIM * EDIM];    // We^T [l][n=256][k=64]
__device__ float g_eloop[NLAYER * HIDDIM];
__device__ float g_esum[EDIM];
__device__ float g_gsum[(size_t)GDIM * HIDDIM];
__device__ float g_gcnt[GDIM];
// CSR (dst-sorted edges)
__device__ int g_cnt[NNODES];
__device__ int g_bsum[512];
__device__ int g_rowptr[NNODES + 1];
__device__ int g_woff[NNODES];
__device__ int g_ssrc[NEDGES];
__device__ int g_seid[NEDGES];

// ---------------- helpers ----------------
__device__ __forceinline__ void red4(float* p, float a, float b, float c, float d) {
    asm volatile("red.global.add.v4.f32 [%0], {%1,%2,%3,%4};"
                 :: "l"(p), "f"(a), "f"(b), "f"(c), "f"(d) : "memory");
}
__device__ __forceinline__ void mma_f16(float* c, const uint32_t* a, const uint32_t* b) {
    asm volatile("mma.sync.aligned.m16n8k16.row.col.f32.f16.f16.f32 "
                 "{%0,%1,%2,%3}, {%4,%5,%6,%7}, {%8,%9}, {%0,%1,%2,%3};"
                 : "+f"(c[0]), "+f"(c[1]), "+f"(c[2]), "+f"(c[3])
                 : "r"(a[0]), "r"(a[1]), "r"(a[2]), "r"(a[3]), "r"(b[0]), "r"(b[1]));
}
__device__ __forceinline__ void cp16(void* smem, const void* gmem) {
    uint32_t s;
    asm("{ .reg .u64 t; cvta.to.shared.u64 t, %1; cvt.u32.u64 %0, t; }" : "=r"(s) : "l"(smem));
    asm volatile("cp.async.cg.shared.global [%0], [%1], 16;" :: "r"(s), "l"(gmem));
}
// XOR swizzle: 32-fp16 row split into 4 chunks of 8; permute chunks by (row>>1)&3.
__device__ __forceinline__ int swz(int row, int col) {
    return ((((col >> 3) ^ ((row >> 1) & 3)) << 3) | (col & 7));
}
__device__ __forceinline__ uint4 pack8h(float4 a, float4 b) {
    uint4 u;
    *(__half2*)&u.x = __floats2half2_rn(a.x, a.y);
    *(__half2*)&u.y = __floats2half2_rn(a.z, a.w);
    *(__half2*)&u.z = __floats2half2_rn(b.x, b.y);
    *(__half2*)&u.w = __floats2half2_rn(b.z, b.w);
    return u;
}
__device__ __forceinline__ void fp16x8_expand(uint4 u, float4& o0, float4& o1) {
    float2 f0 = __half22float2(*(__half2*)&u.x);
    float2 f1 = __half22float2(*(__half2*)&u.y);
    float2 f2 = __half22float2(*(__half2*)&u.z);
    float2 f3 = __half22float2(*(__half2*)&u.w);
    o0 = make_float4(f0.x, f0.y, f1.x, f1.y);
    o1 = make_float4(f2.x, f2.y, f3.x, f3.y);
}

// ========== fp16 GEMM: cp.async 2-stage, BK=32, CTA 128x128, 8 warps 4x2 ==========
// A16: [M][K] fp16 row-major. Bt16: [256][K] fp16 (pre-transposed weights).
#define GEMM_LOAD16(s, k0, Ap, Bp, K, M, row0, col0)                                  \
    _Pragma("unroll") for (int i = 0; i < 2; i++) {                                   \
        int idx = tid + i * 256;                                                      \
        int r = idx >> 2, q = (idx & 3) * 8;                                          \
        int ar = (row0) + r; if (ar >= (M)) ar = (M) - 1;                             \
        cp16(&As[s][r][swz(r, q)], (Ap) + (size_t)ar * (K) + (k0) + q);               \
        cp16(&Bs[s][r][swz(r, q)], (Bp) + (size_t)((col0) + r) * (K) + (k0) + q);     \
    }                                                                                 \
    asm volatile("cp.async.commit_group;" ::: "memory");

#define GEMM_BODY16(Ap, Bp, K, M, row0, col0)                                          \
    float acc[2][8][4];                                                               \
    _Pragma("unroll") for (int mt = 0; mt < 2; mt++)                                  \
    _Pragma("unroll") for (int nt = 0; nt < 8; nt++)                                  \
    _Pragma("unroll") for (int i = 0; i < 4; i++) acc[mt][nt][i] = 0.0f;              \
    GEMM_LOAD16(0, 0, Ap, Bp, K, M, row0, col0)                                       \
    const int NKC = (K) / 32;                                                         \
    for (int kc = 0; kc < NKC; kc++) {                                                \
        if (kc + 1 < NKC) {                                                           \
            GEMM_LOAD16((kc + 1) & 1, (kc + 1) * 32, Ap, Bp, K, M, row0, col0)        \
            asm volatile("cp.async.wait_group 1;" ::: "memory");                      \
        } else {                                                                      \
            asm volatile("cp.async.wait_group 0;" ::: "memory");                      \
        }                                                                             \
        __syncthreads();                                                              \
        const int st = kc & 1;                                                        \
        _Pragma("unroll") for (int ks = 0; ks < 2; ks++) {                            \
            const int kb = ks * 16;                                                   \
            uint32_t bf[8][2];                                                        \
            _Pragma("unroll") for (int nt = 0; nt < 8; nt++) {                        \
                const int bn = warp_n * 64 + nt * 8 + lq;                             \
                bf[nt][0] = *(const uint32_t*)&Bs[st][bn][swz(bn, kb + lr * 2)];      \
                bf[nt][1] = *(const uint32_t*)&Bs[st][bn][swz(bn, kb + lr * 2 + 8)];  \
            }                                                                         \
            _Pragma("unroll") for (int mt = 0; mt < 2; mt++) {                        \
                const int ar = warp_m * 32 + mt * 16 + lq;                            \
                uint32_t af[4];                                                       \
                af[0] = *(const uint32_t*)&As[st][ar][swz(ar, kb + lr * 2)];          \
                af[1] = *(const uint32_t*)&As[st][ar + 8][swz(ar + 8, kb + lr * 2)];  \
                af[2] = *(const uint32_t*)&As[st][ar][swz(ar, kb + lr * 2 + 8)];      \
                af[3] = *(const uint32_t*)&As[st][ar + 8][swz(ar + 8, kb + lr * 2 + 8)]; \
                _Pragma("unroll") for (int nt = 0; nt < 8; nt++)                      \
                    mma_f16(acc[mt][nt], af, bf[nt]);                                 \
            }                                                                         \
        }                                                                             \
        __syncthreads();                                                              \
    }

// ---------------- fused node GEMM: xl = A@Wl+bl, xr = A@Wr+br (fp16 in/out) ----------------
__global__ __launch_bounds__(256)
void gemm_node(const __half* __restrict__ A,
               const __half* __restrict__ Wlt, const __half* __restrict__ Wrt,
               const float* __restrict__ bl_, const float* __restrict__ br_,
               __half* __restrict__ Cl, __half* __restrict__ Cr, int M) {
    __shared__ __align__(16) __half As[2][128][32];
    __shared__ __align__(16) __half Bs[2][128][32];
    const int tid = threadIdx.x, warp = tid >> 5, lane = tid & 31;
    const int warp_m = warp & 3, warp_n = warp >> 2;
    const int row0 = blockIdx.x * 128;
    const int col0 = (blockIdx.y & 1) * 128;
    const __half* W   = (blockIdx.y < 2) ? Wlt : Wrt;
    const float* bias = (blockIdx.y < 2) ? bl_ : br_;
    __half* C         = (blockIdx.y < 2) ? Cl  : Cr;
    const int lq = lane >> 2, lr = lane & 3;

    GEMM_BODY16(A, W, 256, M, row0, col0)

    const int r_base = row0 + warp_m * 32 + lq;
    const int c_base = col0 + warp_n * 64 + lr * 2;
#pragma unroll
    for (int nt = 0; nt < 8; nt++) {
        int c = c_base + nt * 8;
        float2 bv = *(const float2*)(bias + c);
#pragma unroll
        for (int mt = 0; mt < 2; mt++) {
            int r = r_base + mt * 16;
            if (r < M) {
                __half2 v = __floats2half2_rn(acc[mt][nt][0] + bv.x, acc[mt][nt][1] + bv.y);
                *(__half2*)(C + (size_t)r * 256 + c) = v;
            }
            if (r + 8 < M) {
                __half2 v = __floats2half2_rn(acc[mt][nt][2] + bv.x, acc[mt][nt][3] + bv.y);
                *(__half2*)(C + (size_t)(r + 8) * 256 + c) = v;
            }
        }
    }
}

// ---------------- edge GEMM: eproj[i] = (ea16 @ We)[i], CSR row order, fp16 ----------------
__global__ __launch_bounds__(256)
void gemm_edge(const __half* __restrict__ Wet) {
    __shared__ __align__(16) __half As[2][128][32];
    __shared__ __align__(16) __half Bs[2][128][32];
    const __half* A = g_ea16;
    const int tid = threadIdx.x, warp = tid >> 5, lane = tid & 31;
    const int warp_m = warp & 3, warp_n = warp >> 2;
    const int row0 = blockIdx.x * 128;
    const int col0 = blockIdx.y * 128;
    const int lq = lane >> 2, lr = lane & 3;
    const int M = NEDGES;

    GEMM_BODY16(A, Wet, 64, M, row0, col0)

    const int r_base = row0 + warp_m * 32 + lq;
    const int c_base = col0 + warp_n * 64 + lr * 2;
#pragma unroll
    for (int nt = 0; nt < 8; nt++) {
        int c = c_base + nt * 8;
#pragma unroll
        for (int mt = 0; mt < 2; mt++) {
            int r = r_base + mt * 16;
            if (r < M) {
                __half2 v = __floats2half2_rn(acc[mt][nt][0], acc[mt][nt][1]);
                *(__half2*)(g_eproj + (size_t)r * 256 + c) = v;
            }
            if (r + 8 < M) {
                __half2 v = __floats2half2_rn(acc[mt][nt][2], acc[mt][nt][3]);
                *(__half2*)(g_eproj + (size_t)(r + 8) * 256 + c) = v;
            }
        }
    }
}

// ---------------- conversion kernels (once per launch) ----------------
__global__ void convx_kernel(const float* __restrict__ x) {
    int i = blockIdx.x * blockDim.x + threadIdx.x;   // over N*32 chunks of 8 floats
    if (i >= NNODES * 32) return;
    const float4* s = (const float4*)x + (size_t)i * 2;
    ((uint4*)g_x16)[i] = pack8h(s[0], s[1]);
}
// W [l][K][256] fp32 -> Wt [l][256][K] fp16
__global__ void convw_kernel(const float* __restrict__ W, __half* __restrict__ Wt, int K) {
    __shared__ float t[32][33];
    int l = blockIdx.z;
    const float* Wl = W + (size_t)l * K * 256;
    __half* Wtl = Wt + (size_t)l * K * 256;
    int n0 = blockIdx.x * 32, k0 = blockIdx.y * 32;
    int tx = threadIdx.x, ty = threadIdx.y;
#pragma unroll
    for (int j = 0; j < 32; j += 8) t[ty + j][tx] = Wl[(size_t)(k0 + ty + j) * 256 + n0 + tx];
    __syncthreads();
#pragma unroll
    for (int j = 0; j < 32; j += 8)
        Wtl[(size_t)(n0 + ty + j) * K + k0 + tx] = __float2half(t[tx][ty + j]);
}

// ---------------- CSR build (once per launch) ----------------
__global__ void hist_kernel(const int* __restrict__ dst) {
    int e = blockIdx.x * blockDim.x + threadIdx.x;
    if (e < NEDGES) atomicAdd(&g_cnt[dst[e]], 1);
}
__global__ void blocksum_kernel() {
    int i = blockIdx.x * 256 + threadIdx.x;
    int v = (i < NNODES) ? g_cnt[i] : 0;
    __shared__ int ws[8];
#pragma unroll
    for (int o = 16; o; o >>= 1) v += __shfl_down_sync(0xffffffffu, v, o);
    if ((threadIdx.x & 31) == 0) ws[threadIdx.x >> 5] = v;
    __syncthreads();
    if (threadIdx.x == 0) {
        int s = 0;
#pragma unroll
        for (int j = 0; j < 8; j++) s += ws[j];
        g_bsum[blockIdx.x] = s;
    }
}
__global__ void scanb_kernel() {
    __shared__ int sm[512];
    int i = threadIdx.x;
    int v = (i < NBLK) ? g_bsum[i] : 0;
    sm[i] = v;
    __syncthreads();
    for (int s = 1; s < 512; s <<= 1) {
        int t = (i >= s) ? sm[i - s] : 0;
        __syncthreads();
        sm[i] += t;
        __syncthreads();
    }
    if (i < NBLK) g_bsum[i] = sm[i] - v;
}
__global__ void rowptr_kernel() {
    int tid = threadIdx.x;
    int i = blockIdx.x * 256 + tid;
    int v = (i < NNODES) ? g_cnt[i] : 0;
    __shared__ int sm[256];
    sm[tid] = v;
    __syncthreads();
    for (int s = 1; s < 256; s <<= 1) {
        int t = (tid >= s) ? sm[tid - s] : 0;
        __syncthreads();
        sm[tid] += t;
        __syncthreads();
    }
    int ex = sm[tid] - v + g_bsum[blockIdx.x];
    if (i < NNODES) { g_rowptr[i] = ex; g_woff[i] = ex; }
    if (i == NNODES - 1) g_rowptr[NNODES] = NEDGES;
}
__global__ void fill_kernel(const int* __restrict__ src, const int* __restrict__ dst) {
    int e = blockIdx.x * blockDim.x + threadIdx.x;
    if (e >= NEDGES) return;
    int d = dst[e];
    int pos = atomicAdd(&g_woff[d], 1);
    g_ssrc[pos] = src[e];
    g_seid[pos] = e;
}
// permute edge_attr into dst-sorted order, converting to fp16
__global__ void permute_ea_kernel(const float* __restrict__ ea) {
    int gt = blockIdx.x * blockDim.x + threadIdx.x;   // NEDGES*8 chunks of 8 floats
    if (gt >= NEDGES * 8) return;
    int i = gt >> 3, q = gt & 7;
    int e = g_seid[i];
    const float4* s = (const float4*)(ea + (size_t)e * 64 + q * 8);
    ((uint4*)g_ea16)[(size_t)i * 8 + q] = pack8h(s[0], s[1]);
}

// ---------------- edge_attr column sums + eloop (all layers upfront) ----------------
__global__ void esum_kernel(const float* __restrict__ ea) {
    int col = threadIdx.x & 63;
    int rowsPerBlk = blockDim.x >> 6;
    int r0 = blockIdx.x * rowsPerBlk + (threadIdx.x >> 6);
    int rstride = gridDim.x * rowsPerBlk;
    float s = 0.0f;
    for (int r = r0; r < NEDGES; r += rstride) s += ea[(size_t)r * EDIM + col];
    atomicAdd(&g_esum[col], s);
}
__global__ void eloop_kernel(const float* __restrict__ We) {
    int l = blockIdx.x;
    int j = threadIdx.x;
    const float* W = We + (size_t)l * EDIM * 256;
    const float inv = 1.0f / (float)NEDGES;
    float acc = 0.0f;
#pragma unroll
    for (int k = 0; k < EDIM; k++) acc = fmaf(g_esum[k] * inv, W[k * 256 + j], acc);
    g_eloop[l * 256 + j] = acc;
}

// ---------------- fused GAT edge phase: warp per dst node, 2-deep edge pipeline ----------------
__global__ __launch_bounds__(256)
void fused_gat_kernel(const float* __restrict__ att, const float* __restrict__ bias,
                      const float* __restrict__ eloop, __half* __restrict__ xn) {
    int gt = blockIdx.x * blockDim.x + threadIdx.x;
    int d = gt >> 5, lane = gt & 31;
    if (d >= NNODES) return;
    const int off = lane * 8;

    float4 xr0, xr1;
    fp16x8_expand(*(const uint4*)(g_xr + (size_t)d * 256 + off), xr0, xr1);
    float4 at0 = *(const float4*)(att + off);
    float4 at1 = *(const float4*)(att + off + 4);

    float acc[8];
    float denom;
    // ---- self loop: src = d, edge feature = eloop (fp32) ----
    {
        float4 a0, a1;
        fp16x8_expand(*(const uint4*)(g_xl + (size_t)d * 256 + off), a0, a1);
        float4 e0 = *(const float4*)(eloop + off);
        float4 e1 = *(const float4*)(eloop + off + 4);
        float t = 0.0f, m;
        m = a0.x + xr0.x + e0.x; m = fmaxf(m, 0.2f * m); t = fmaf(m, at0.x, t);
        m = a0.y + xr0.y + e0.y; m = fmaxf(m, 0.2f * m); t = fmaf(m, at0.y, t);
        m = a0.z + xr0.z + e0.z; m = fmaxf(m, 0.2f * m); t = fmaf(m, at0.z, t);
        m = a0.w + xr0.w + e0.w; m = fmaxf(m, 0.2f * m); t = fmaf(m, at0.w, t);
        m = a1.x + xr1.x + e1.x; m = fmaxf(m, 0.2f * m); t = fmaf(m, at1.x, t);
        m = a1.y + xr1.y + e1.y; m = fmaxf(m, 0.2f * m); t = fmaf(m, at1.y, t);
        m = a1.z + xr1.z + e1.z; m = fmaxf(m, 0.2f * m); t = fmaf(m, at1.z, t);
        m = a1.w + xr1.w + e1.w; m = fmaxf(m, 0.2f * m); t = fmaf(m, at1.w, t);
        t += __shfl_down_sync(0xffffffffu, t, 4, 8);
        t += __shfl_down_sync(0xffffffffu, t, 2, 8);
        t += __shfl_down_sync(0xffffffffu, t, 1, 8);
        float p = __expf(__shfl_sync(0xffffffffu, t, 0, 8));
        denom = p;
        acc[0] = p * a0.x; acc[1] = p * a0.y; acc[2] = p * a0.z; acc[3] = p * a0.w;
        acc[4] = p * a1.x; acc[5] = p * a1.y; acc[6] = p * a1.z; acc[7] = p * a1.w;
    }
    // ---- real edges: CSR order, prefetch next edge while computing current ----
    const int beg = g_rowptr[d], end = g_rowptr[d + 1];
    uint4 au, eu;
    if (beg < end) {
        int s = g_ssrc[beg];
        au = *(const uint4*)(g_xl + (size_t)s * 256 + off);
        eu = *(const uint4*)(g_eproj + (size_t)beg * 256 + off);
    }
    for (int i = beg; i < end; i++) {
        uint4 a_cur = au, e_cur = eu;
        if (i + 1 < end) {
            int s = g_ssrc[i + 1];
            au = *(const uint4*)(g_xl + (size_t)s * 256 + off);
            eu = *(const uint4*)(g_eproj + (size_t)(i + 1) * 256 + off);
        }
        float4 a0, a1, e0, e1;
        fp16x8_expand(a_cur, a0, a1);
        fp16x8_expand(e_cur, e0, e1);
        float t = 0.0f, m;
        m = a0.x + xr0.x + e0.x; m = fmaxf(m, 0.2f * m); t = fmaf(m, at0.x, t);
        m = a0.y + xr0.y + e0.y; m = fmaxf(m, 0.2f * m); t = fmaf(m, at0.y, t);
        m = a0.z + xr0.z + e0.z; m = fmaxf(m, 0.2f * m); t = fmaf(m, at0.z, t);
        m = a0.w + xr0.w + e0.w; m = fmaxf(m, 0.2f * m); t = fmaf(m, at0.w, t);
        m = a1.x + xr1.x + e1.x; m = fmaxf(m, 0.2f * m); t = fmaf(m, at1.x, t);
        m = a1.y + xr1.y + e1.y; m = fmaxf(m, 0.2f * m); t = fmaf(m, at1.y, t);
        m = a1.z + xr1.z + e1.z; m = fmaxf(m, 0.2f * m); t = fmaf(m, at1.z, t);
        m = a1.w + xr1.w + e1.w; m = fmaxf(m, 0.2f * m); t = fmaf(m, at1.w, t);
        t += __shfl_down_sync(0xffffffffu, t, 4, 8);
        t += __shfl_down_sync(0xffffffffu, t, 2, 8);
        t += __shfl_down_sync(0xffffffffu, t, 1, 8);
        float p = __expf(__shfl_sync(0xffffffffu, t, 0, 8));
        denom += p;
        acc[0] = fmaf(p, a0.x, acc[0]); acc[1] = fmaf(p, a0.y, acc[1]);
        acc[2] = fmaf(p, a0.z, acc[2]); acc[3] = fmaf(p, a0.w, acc[3]);
        acc[4] = fmaf(p, a1.x, acc[4]); acc[5] = fmaf(p, a1.y, acc[5]);
        acc[6] = fmaf(p, a1.z, acc[6]); acc[7] = fmaf(p, a1.w, acc[7]);
    }
    float inv = 1.0f / (denom + 1e-16f);
    float4 b0 = *(const float4*)(bias + off);
    float4 b1 = *(const float4*)(bias + off + 4);
    float4 o0, o1;
    o0.x = fmaxf(fmaf(acc[0], inv, b0.x), 0.f); o0.y = fmaxf(fmaf(acc[1], inv, b0.y), 0.f);
    o0.z = fmaxf(fmaf(acc[2], inv, b0.z), 0.f); o0.w = fmaxf(fmaf(acc[3], inv, b0.w), 0.f);
    o1.x = fmaxf(fmaf(acc[4], inv, b1.x), 0.f); o1.y = fmaxf(fmaf(acc[5], inv, b1.y), 0.f);
    o1.z = fmaxf(fmaf(acc[6], inv, b1.z), 0.f); o1.w = fmaxf(fmaf(acc[7], inv, b1.w), 0.f);
    *(uint4*)(xn + (size_t)d * 256 + off) = pack8h(o0, o1);
}

// ---------------- global mean pool (fp16 input) ----------------
__global__ void pool_kernel(const int* __restrict__ batch, const __half* __restrict__ xf) {
    int gt = blockIdx.x * blockDim.x + threadIdx.x;
    int node = gt >> 5, lane = gt & 31;
    if (node >= NNODES) return;
    int g = batch[node];
    float4 v0, v1;
    fp16x8_expand(*(const uint4*)(xf + (size_t)node * 256 + lane * 8), v0, v1);
    float* bp = g_gsum + (size_t)g * 256 + lane * 8;
    red4(bp,     v0.x, v0.y, v0.z, v0.w);
    red4(bp + 4, v1.x, v1.y, v1.z, v1.w);
    if (lane == 0) atomicAdd(&g_gcnt[g], 1.0f);
}

// ---------------- final MLP ----------------
__global__ __launch_bounds__(128)
void mlp_kernel(const float* __restrict__ Wp1, const float* __restrict__ bp1,
                const float* __restrict__ Wp2, const float* __restrict__ bp2,
                float* __restrict__ out) {
    int g = blockIdx.x;
    __shared__ float pooled[256];
    __shared__ float partial[4];
    float cnt = fmaxf(g_gcnt[g], 1.0f);
    for (int i = threadIdx.x; i < 256; i += 128)
        pooled[i] = g_gsum[(size_t)g * 256 + i] / cnt;
    __syncthreads();
    int j = threadIdx.x;
    float acc = bp1[j];
#pragma unroll 8
    for (int k = 0; k < 256; k++) acc = fmaf(pooled[k], Wp1[k * 128 + j], acc);
    float h = fmaxf(acc, 0.0f) * Wp2[j];
#pragma unroll
    for (int o = 16; o; o >>= 1) h += __shfl_down_sync(0xffffffffu, h, o);
    if ((threadIdx.x & 31) == 0) partial[threadIdx.x >> 5] = h;
    __syncthreads();
    if (threadIdx.x == 0)
        out[g] = partial[0] + partial[1] + partial[2] + partial[3] + bp2[0];
}

// ---------------- launcher ----------------
extern "C" void kernel_launch(void* const* d_in, const int* in_sizes, int n_in,
                              void* d_out, int out_size) {
    const float* x     = (const float*)d_in[0];
    const int*   ei    = (const int*)  d_in[1];
    const float* ea    = (const float*)d_in[2];
    const int*   batch = (const int*)  d_in[3];
    const float* Wl    = (const float*)d_in[4];
    const float* bl    = (const float*)d_in[5];
    const float* Wr    = (const float*)d_in[6];
    const float* br    = (const float*)d_in[7];
    const float* We    = (const float*)d_in[8];
    const float* att   = (const float*)d_in[9];
    const float* bias  = (const float*)d_in[10];
    const float* Wp1   = (const float*)d_in[11];
    const float* bp1   = (const float*)d_in[12];
    const float* Wp2   = (const float*)d_in[13];
    const float* bp2   = (const float*)d_in[14];
    float* out = (float*)d_out;
    const int* src = ei;
    const int* dst = ei + NEDGES;

    float *esum, *gsum, *gcnt, *eloop;
    __half *x16, *b16A, *b16B, *xl, *xr, *wlt, *wrt, *wet;
    int* cnt;
    cudaGetSymbolAddress((void**)&x16,  g_x16);
    cudaGetSymbolAddress((void**)&b16A, g_buf16A);
    cudaGetSymbolAddress((void**)&b16B, g_buf16B);
    cudaGetSymbolAddress((void**)&xl,   g_xl);
    cudaGetSymbolAddress((void**)&xr,   g_xr);
    cudaGetSymbolAddress((void**)&wlt,  g_wlt);
    cudaGetSymbolAddress((void**)&wrt,  g_wrt);
    cudaGetSymbolAddress((void**)&wet,  g_wet);
    cudaGetSymbolAddress((void**)&esum, g_esum);
    cudaGetSymbolAddress((void**)&gsum, g_gsum);
    cudaGetSymbolAddress((void**)&gcnt, g_gcnt);
    cudaGetSymbolAddress((void**)&eloop, g_eloop);
    cudaGetSymbolAddress((void**)&cnt,  g_cnt);

    // ---- CSR build + conversions (topology/weights constant) ----
    cudaMemsetAsync(cnt, 0, NNODES * sizeof(int));
    hist_kernel<<<(NEDGES + 255) / 256, 256>>>(dst);
    blocksum_kernel<<<NBLK, 256>>>();
    scanb_kernel<<<1, 512>>>();
    rowptr_kernel<<<NBLK, 256>>>();
    fill_kernel<<<(NEDGES + 255) / 256, 256>>>(src, dst);
    permute_ea_kernel<<<(NEDGES * 8 + 255) / 256, 256>>>(ea);

    convx_kernel<<<(NNODES * 32 + 255) / 256, 256>>>(x);
    dim3 tb(32, 8);
    convw_kernel<<<dim3(8, 8, 3), tb>>>(Wl, wlt, 256);
    convw_kernel<<<dim3(8, 8, 3), tb>>>(Wr, wrt, 256);
    convw_kernel<<<dim3(8, 2, 3), tb>>>(We, wet, 64);

    cudaMemsetAsync(esum, 0, EDIM * sizeof(float));
    esum_kernel<<<512, 256>>>(ea);
    eloop_kernel<<<NLAYER, 256>>>(We);

    const __half* xcur = x16;
    for (int l = 0; l < NLAYER; l++) {
        __half* xn = (l & 1) ? b16B : b16A;
        dim3 gN((NNODES + 127) / 128, 4);
        gemm_node<<<gN, 256>>>(xcur, wlt + (size_t)l * 256 * 256, wrt + (size_t)l * 256 * 256,
                               bl + l * 256, br + l * 256, xl, xr, NNODES);
        dim3 gE((NEDGES + 127) / 128, 2);
        gemm_edge<<<gE, 256>>>(wet + (size_t)l * 64 * 256);

        fused_gat_kernel<<<(NNODES * 32 + 255) / 256, 256>>>(att + l * 256, bias + l * 256,
                                                             eloop + l * 256, xn);
        xcur = xn;
    }

    cudaMemsetAsync(gsum, 0, (size_t)GDIM * 256 * sizeof(float));
    cudaMemsetAsync(gcnt, 0, GDIM * sizeof(float));
    pool_kernel<<<(NNODES * 32 + 255) / 256, 256>>>(batch, xcur);
    mlp_kernel<<<GDIM, 128>>>(Wp1, bp1, Wp2, bp2, out);
}